// round 1
// baseline (speedup 1.0000x reference)
#include <cuda_runtime.h>
#include <math.h>
#include <math_constants.h>

// Problem constants
constexpr int cB = 4;
constexpr int cS = 2048;
constexpr int cH = 2048;
constexpr int cH2 = cH / 2;
constexpr int cM = cB * cS;           // 8192 rows for the big projections
constexpr size_t SH = (size_t)cS * cH;    // 4,194,304
constexpr size_t SS = (size_t)cS * cS;    // 4,194,304
constexpr size_t MH = (size_t)cM * cH;    // 16,777,216

// ---------------- scratch (device globals; no allocation allowed) ----------
__device__ float g_cos[SH];
__device__ float g_sin[SH];
__device__ float g_qrot[MH];
__device__ float g_krot[MH];
__device__ float g_q[MH];
__device__ float g_k[MH];
__device__ float g_v[MH];
__device__ float g_s[(size_t)cB * SS];   // scores -> probs (in place)
__device__ float g_ctx[MH];

// ---------------- RoPE tables ---------------------------------------------
// emb[s, j] = emb[s, j+H/2] = s * inv_freq[j],  inv_freq[j] = 10000^(-2j/H)
__global__ void rope_tables_kernel() {
    int idx = blockIdx.x * blockDim.x + threadIdx.x;
    if (idx >= cS * cH2) return;
    int s = idx / cH2;
    int j = idx % cH2;
    float f = (float)pow(10000.0, -2.0 * (double)j / (double)cH);
    float ang = (float)s * f;
    float sn, cs;
    sincosf(ang, &sn, &cs);
    size_t base = (size_t)s * cH + j;
    g_cos[base] = cs; g_cos[base + cH2] = cs;
    g_sin[base] = sn; g_sin[base + cH2] = sn;
}

// ---------------- RoPE apply (q and k together) ----------------------------
__global__ void rope_apply_kernel(const float* __restrict__ q,
                                  const float* __restrict__ k) {
    size_t idx = (size_t)blockIdx.x * blockDim.x + threadIdx.x;
    if (idx >= MH) return;
    size_t sh = idx % SH;            // (s,h) index
    int h = (int)(idx % cH);
    float c = g_cos[sh];
    float s_ = g_sin[sh];
    float qv = q[idx];
    float kv = k[idx];
    float qr, kr;
    if (h < cH2) { qr = -q[idx + cH2]; kr = -k[idx + cH2]; }
    else         { qr =  q[idx - cH2]; kr =  k[idx - cH2]; }
    g_qrot[idx] = qv * c + qr * s_;
    g_krot[idx] = kv * c + kr * s_;
}

// ---------------- tiled fp32 GEMM ------------------------------------------
// C[m,n] = sum_k A[m,k] * B'[k,n] (+ bias[n])
// TRANSB=true : B stored [N,K] row-major (K contiguous)  -> C = A @ B^T
// TRANSB=false: B stored [K,N] row-major (N contiguous)  -> C = A @ B
// Dimensions must be multiples of the tile (they are: 2048/8192).
template<bool TRANSB, bool BIAS>
__global__ __launch_bounds__(256, 2)
void gemm_f32(const float* __restrict__ A, const float* __restrict__ Bm,
              const float* __restrict__ bias, float* __restrict__ C,
              int Md, int Nd, int Kd,
              size_t strA, size_t strB, size_t strC) {
    __shared__ float As[8][128];
    __shared__ float Bs[8][128];

    const int tid = threadIdx.x;
    const float* Ab = A + (size_t)blockIdx.z * strA;
    const float* Bb = Bm + (size_t)blockIdx.z * strB;
    float* Cb = C + (size_t)blockIdx.z * strC;

    const int bm = blockIdx.y * 128;
    const int bn = blockIdx.x * 128;

    // loaders (K-contiguous tiles): 128 rows x 8 cols -> one float4 per thread
    const int lr = tid >> 1;            // 0..127
    const int lc = (tid & 1) * 4;       // 0 or 4
    // loader for NN B tile: 8 rows x 128 cols
    const int nr = tid >> 5;            // 0..7
    const int nc = (tid & 31) * 4;      // 0..124

    const int ty = tid >> 4;            // 0..15  (row tile)
    const int tx = tid & 15;            // 0..15  (col tile)

    float acc[8][8];
#pragma unroll
    for (int i = 0; i < 8; i++)
#pragma unroll
        for (int j = 0; j < 8; j++) acc[i][j] = 0.f;

    for (int k0 = 0; k0 < Kd; k0 += 8) {
        float4 av = *(const float4*)(Ab + (size_t)(bm + lr) * Kd + k0 + lc);
        As[lc + 0][lr] = av.x; As[lc + 1][lr] = av.y;
        As[lc + 2][lr] = av.z; As[lc + 3][lr] = av.w;
        if (TRANSB) {
            float4 bv = *(const float4*)(Bb + (size_t)(bn + lr) * Kd + k0 + lc);
            Bs[lc + 0][lr] = bv.x; Bs[lc + 1][lr] = bv.y;
            Bs[lc + 2][lr] = bv.z; Bs[lc + 3][lr] = bv.w;
        } else {
            float4 bv = *(const float4*)(Bb + (size_t)(k0 + nr) * Nd + bn + nc);
            *(float4*)&Bs[nr][nc] = bv;
        }
        __syncthreads();
#pragma unroll
        for (int kk = 0; kk < 8; kk++) {
            float ra[8], rb[8];
            *(float4*)(ra)     = *(const float4*)&As[kk][ty * 8];
            *(float4*)(ra + 4) = *(const float4*)&As[kk][ty * 8 + 4];
            *(float4*)(rb)     = *(const float4*)&Bs[kk][tx * 8];
            *(float4*)(rb + 4) = *(const float4*)&Bs[kk][tx * 8 + 4];
#pragma unroll
            for (int i = 0; i < 8; i++)
#pragma unroll
                for (int j = 0; j < 8; j++)
                    acc[i][j] += ra[i] * rb[j];
        }
        __syncthreads();
    }

    // epilogue
#pragma unroll
    for (int i = 0; i < 8; i++) {
        const int row = bm + ty * 8 + i;
        float o[8];
#pragma unroll
        for (int j = 0; j < 8; j++) {
            float v = acc[i][j];
            if (BIAS) v += bias[bn + tx * 8 + j];
            o[j] = v;
        }
        float* cp = Cb + (size_t)row * Nd + bn + tx * 8;
        *(float4*)(cp)     = *(float4*)(o);
        *(float4*)(cp + 4) = *(float4*)(o + 4);
    }
}

// ---------------- softmax over rows of length 2048 -------------------------
__global__ void softmax_kernel(float* __restrict__ Sc, float scale) {
    const size_t row = blockIdx.x;
    float* p = Sc + row * (size_t)cS;
    const int tid = threadIdx.x;
    __shared__ float smax[8];
    __shared__ float ssum[8];

    float v[8];
    float m = -CUDART_INF_F;
#pragma unroll
    for (int i = 0; i < 8; i++) {
        v[i] = p[tid + i * 256] * scale;
        m = fmaxf(m, v[i]);
    }
#pragma unroll
    for (int o = 16; o > 0; o >>= 1)
        m = fmaxf(m, __shfl_xor_sync(0xffffffffu, m, o));
    if ((tid & 31) == 0) smax[tid >> 5] = m;
    __syncthreads();
    m = smax[0];
#pragma unroll
    for (int w = 1; w < 8; w++) m = fmaxf(m, smax[w]);

    float s = 0.f;
#pragma unroll
    for (int i = 0; i < 8; i++) {
        v[i] = expf(v[i] - m);
        s += v[i];
    }
#pragma unroll
    for (int o = 16; o > 0; o >>= 1)
        s += __shfl_xor_sync(0xffffffffu, s, o);
    if ((tid & 31) == 0) ssum[tid >> 5] = s;
    __syncthreads();
    s = 0.f;
#pragma unroll
    for (int w = 0; w < 8; w++) s += ssum[w];
    const float inv = 1.0f / s;
#pragma unroll
    for (int i = 0; i < 8; i++) p[tid + i * 256] = v[i] * inv;
}

// ---------------- launch ----------------------------------------------------
extern "C" void kernel_launch(void* const* d_in, const int* in_sizes, int n_in,
                              void* d_out, int out_size) {
    const float* query = (const float*)d_in[0];
    const float* key_  = (const float*)d_in[1];
    const float* value = (const float*)d_in[2];
    const float* Wq = (const float*)d_in[3];
    const float* bq = (const float*)d_in[4];
    const float* Wk = (const float*)d_in[5];
    const float* bk = (const float*)d_in[6];
    const float* Wv = (const float*)d_in[7];
    const float* bv = (const float*)d_in[8];
    const float* Wo = (const float*)d_in[9];
    const float* bo = (const float*)d_in[10];
    float* out = (float*)d_out;

    float *p_qrot, *p_krot, *p_q, *p_k, *p_v, *p_s, *p_ctx;
    cudaGetSymbolAddress((void**)&p_qrot, g_qrot);
    cudaGetSymbolAddress((void**)&p_krot, g_krot);
    cudaGetSymbolAddress((void**)&p_q, g_q);
    cudaGetSymbolAddress((void**)&p_k, g_k);
    cudaGetSymbolAddress((void**)&p_v, g_v);
    cudaGetSymbolAddress((void**)&p_s, g_s);
    cudaGetSymbolAddress((void**)&p_ctx, g_ctx);

    // 1) RoPE tables + apply
    rope_tables_kernel<<<(cS * cH2 + 255) / 256, 256>>>();
    rope_apply_kernel<<<(int)((MH + 255) / 256), 256>>>(query, key_);

    // 2) projections: x @ W^T + b   (M=8192, N=2048, K=2048)
    dim3 gproj(cH / 128, cM / 128, 1);
    gemm_f32<true, true><<<gproj, 256>>>(p_qrot, Wq, bq, p_q, cM, cH, cH, 0, 0, 0);
    gemm_f32<true, true><<<gproj, 256>>>(p_krot, Wk, bk, p_k, cM, cH, cH, 0, 0, 0);
    gemm_f32<true, true><<<gproj, 256>>>(value,  Wv, bv, p_v, cM, cH, cH, 0, 0, 0);

    // 3) scores = q @ k^T (batched over B)
    dim3 gatt(cS / 128, cS / 128, cB);
    gemm_f32<true, false><<<gatt, 256>>>(p_q, p_k, nullptr, p_s,
                                         cS, cS, cH, SH, SH, SS);

    // 4) softmax(scale * scores) in place
    const float scale = 1.0f / sqrtf((float)cH);
    softmax_kernel<<<cB * cS, 256>>>(p_s, scale);

    // 5) context = probs @ v (batched)
    gemm_f32<false, false><<<gatt, 256>>>(p_s, p_v, nullptr, p_ctx,
                                          cS, cH, cS, SS, SH, SH);

    // 6) out = context @ Wo^T + bo
    gemm_f32<true, true><<<gproj, 256>>>(p_ctx, Wo, bo, out, cM, cH, cH, 0, 0, 0);
}

// round 2
// speedup vs baseline: 2.4803x; 2.4803x over previous
#include <cuda_runtime.h>
#include <math.h>
#include <math_constants.h>
#include <stdint.h>

// Problem constants
constexpr int cB = 4;
constexpr int cS = 2048;
constexpr int cH = 2048;
constexpr int cH2 = cH / 2;
constexpr int cM = cB * cS;               // 8192
constexpr size_t SH = (size_t)cS * cH;    // 4,194,304
constexpr size_t SS = (size_t)cS * cS;
constexpr size_t MH = (size_t)cM * cH;    // 16,777,216
constexpr size_t WN = (size_t)cH * cH;    // 4,194,304

// ---------------- scratch (device globals; no allocation allowed) ----------
__device__ float g_cos[SH];
__device__ float g_sin[SH];
__device__ float g_qrot[MH];
__device__ float g_krot[MH];
__device__ float g_vin[MH];     // tf32-rounded value input
__device__ float g_wq[WN];
__device__ float g_wk[WN];
__device__ float g_wv[WN];
__device__ float g_wo[WN];
__device__ float g_q[MH];
__device__ float g_k[MH];
__device__ float g_v[MH];
__device__ float g_vT[MH];      // v transposed [H][M], tf32-rounded
__device__ float g_s[(size_t)cB * SS];
__device__ float g_ctx[MH];

// ---------------- helpers ---------------------------------------------------
__device__ __forceinline__ float tf32r(float x) {
    uint32_t u;
    asm("cvt.rna.tf32.f32 %0, %1;" : "=r"(u) : "f"(x));
    return __uint_as_float(u);
}

#define CPA16(smem_u32, gptr) \
    asm volatile("cp.async.cg.shared.global [%0], [%1], 16;" :: "r"(smem_u32), "l"(gptr))

// ---------------- RoPE tables ----------------------------------------------
__global__ void rope_tables_kernel() {
    int idx = blockIdx.x * blockDim.x + threadIdx.x;
    if (idx >= cS * cH2) return;
    int s = idx / cH2;
    int j = idx % cH2;
    float f = (float)pow(10000.0, -2.0 * (double)j / (double)cH);
    float ang = (float)s * f;
    float sn, cs;
    sincosf(ang, &sn, &cs);
    size_t base = (size_t)s * cH + j;
    g_cos[base] = cs; g_cos[base + cH2] = cs;
    g_sin[base] = sn; g_sin[base + cH2] = sn;
}

// ---------------- RoPE apply (writes tf32-rounded) --------------------------
__global__ void rope_apply_kernel(const float* __restrict__ q,
                                  const float* __restrict__ k) {
    size_t idx = (size_t)blockIdx.x * blockDim.x + threadIdx.x;
    if (idx >= MH) return;
    size_t sh = idx % SH;
    int h = (int)(idx % cH);
    float c = g_cos[sh];
    float s_ = g_sin[sh];
    float qv = q[idx];
    float kv = k[idx];
    float qr, kr;
    if (h < cH2) { qr = -q[idx + cH2]; kr = -k[idx + cH2]; }
    else         { qr =  q[idx - cH2]; kr =  k[idx - cH2]; }
    g_qrot[idx] = tf32r(qv * c + qr * s_);
    g_krot[idx] = tf32r(kv * c + kr * s_);
}

// ---------------- round-copy (prep weights / value to tf32) -----------------
__global__ void round_copy_kernel(const float* __restrict__ in,
                                  float* __restrict__ out, size_t n4) {
    size_t i = (size_t)blockIdx.x * blockDim.x + threadIdx.x;
    if (i >= n4) return;
    float4 v = ((const float4*)in)[i];
    v.x = tf32r(v.x); v.y = tf32r(v.y); v.z = tf32r(v.z); v.w = tf32r(v.w);
    ((float4*)out)[i] = v;
}

// ---------------- transpose with tf32 rounding ([M][H] -> [H][M]) -----------
__global__ void transpose_round_kernel(const float* __restrict__ in,
                                       float* __restrict__ out) {
    __shared__ float t[32][33];
    int x = blockIdx.x * 32 + threadIdx.x;   // col (H)
    int y0 = blockIdx.y * 32 + threadIdx.y;  // row (M)
#pragma unroll
    for (int j = 0; j < 32; j += 8)
        t[threadIdx.y + j][threadIdx.x] = in[(size_t)(y0 + j) * cH + x];
    __syncthreads();
    int ox = blockIdx.y * 32 + threadIdx.x;  // col of out (M)
    int oy = blockIdx.x * 32 + threadIdx.y;  // row of out (H)
#pragma unroll
    for (int j = 0; j < 32; j += 8)
        out[(size_t)(oy + j) * cM + ox] = tf32r(t[threadIdx.x][threadIdx.y + j]);
}

// ---------------- TF32 tensor-core GEMM -------------------------------------
// C[m,n] = sum_k A[m,k] * B[n,k]  (+ bias[n])   -- B always [N][K] row-major
// All dims multiples of 128 (M,N) and 32 (K). Inputs pre-rounded to tf32.
constexpr int BM = 128, BN = 128, BK = 32, LDS_ = 36;
constexpr int STAGE = BM * LDS_;   // floats per matrix per stage

template<bool BIAS, bool ROUND>
__global__ __launch_bounds__(256)
void gemm_tf32(const float* __restrict__ A, const float* __restrict__ Bm,
               const float* __restrict__ bias, float* __restrict__ C,
               int Nd, int Kd, int lda, int ldb, int ldc,
               size_t strA, size_t strB, size_t strC) {
    extern __shared__ float sm[];
    float* As = sm;                 // 2 stages
    float* Bs = sm + 2 * STAGE;

    const int tid = threadIdx.x;
    const int lane = tid & 31;
    const int w = tid >> 5;
    const int wm = (w >> 2) * 64;   // warp row offset within block
    const int wn = (w & 3) * 32;    // warp col offset
    const int g = lane >> 2;
    const int tig = lane & 3;

    const float* Ab = A + (size_t)blockIdx.z * strA;
    const float* Bb = Bm + (size_t)blockIdx.z * strB;
    float* Cb = C + (size_t)blockIdx.z * strC;
    const int bm = blockIdx.y * BM;
    const int bn = blockIdx.x * BN;

    const int lrow = tid >> 1;            // 0..127
    const int lcol = (tid & 1) * 16;      // 0 or 16 (floats)

    const uint32_t sA0 = (uint32_t)__cvta_generic_to_shared(As) +
                         (uint32_t)((lrow * LDS_ + lcol) * 4);
    const uint32_t sB0 = (uint32_t)__cvta_generic_to_shared(Bs) +
                         (uint32_t)((lrow * LDS_ + lcol) * 4);
    const float* agBase = Ab + (size_t)(bm + lrow) * lda + lcol;
    const float* bgBase = Bb + (size_t)(bn + lrow) * ldb + lcol;

    float acc[4][4][4];
#pragma unroll
    for (int i = 0; i < 4; i++)
#pragma unroll
        for (int j = 0; j < 4; j++)
#pragma unroll
            for (int r = 0; r < 4; r++) acc[i][j][r] = 0.f;

    const int nk = Kd / BK;

    // prefetch tile 0
    {
        const float* ag = agBase;
        const float* bg = bgBase;
#pragma unroll
        for (int i = 0; i < 4; i++) {
            CPA16(sA0 + i * 16, ag + i * 4);
            CPA16(sB0 + i * 16, bg + i * 4);
        }
        asm volatile("cp.async.commit_group;");
    }

    for (int kt = 0; kt < nk; kt++) {
        const int st = kt & 1;
        if (kt + 1 < nk) {
            const int st2 = (kt + 1) & 1;
            const float* ag = agBase + (size_t)(kt + 1) * BK;
            const float* bg = bgBase + (size_t)(kt + 1) * BK;
            const uint32_t o = (uint32_t)(st2 * STAGE * 4);
#pragma unroll
            for (int i = 0; i < 4; i++) {
                CPA16(sA0 + o + i * 16, ag + i * 4);
                CPA16(sB0 + o + i * 16, bg + i * 4);
            }
            asm volatile("cp.async.commit_group;");
            asm volatile("cp.async.wait_group 1;");
        } else {
            asm volatile("cp.async.wait_group 0;");
        }
        __syncthreads();

        const float* as = As + st * STAGE;
        const float* bs = Bs + st * STAGE;
#pragma unroll
        for (int ks = 0; ks < 4; ks++) {
            const int kb = ks * 8;
            uint32_t af[4][4];
#pragma unroll
            for (int i = 0; i < 4; i++) {
                const int r = wm + i * 16;
                af[i][0] = __float_as_uint(as[(r + g) * LDS_ + kb + tig]);
                af[i][1] = __float_as_uint(as[(r + g + 8) * LDS_ + kb + tig]);
                af[i][2] = __float_as_uint(as[(r + g) * LDS_ + kb + tig + 4]);
                af[i][3] = __float_as_uint(as[(r + g + 8) * LDS_ + kb + tig + 4]);
            }
            uint32_t bf[4][2];
#pragma unroll
            for (int j = 0; j < 4; j++) {
                const int c = wn + j * 8;
                bf[j][0] = __float_as_uint(bs[(c + g) * LDS_ + kb + tig]);
                bf[j][1] = __float_as_uint(bs[(c + g) * LDS_ + kb + tig + 4]);
            }
#pragma unroll
            for (int i = 0; i < 4; i++)
#pragma unroll
                for (int j = 0; j < 4; j++) {
                    asm volatile(
                        "mma.sync.aligned.m16n8k8.row.col.f32.tf32.tf32.f32 "
                        "{%0,%1,%2,%3}, {%4,%5,%6,%7}, {%8,%9}, {%0,%1,%2,%3};"
                        : "+f"(acc[i][j][0]), "+f"(acc[i][j][1]),
                          "+f"(acc[i][j][2]), "+f"(acc[i][j][3])
                        : "r"(af[i][0]), "r"(af[i][1]), "r"(af[i][2]), "r"(af[i][3]),
                          "r"(bf[j][0]), "r"(bf[j][1]));
                }
        }
        __syncthreads();
    }

    // epilogue
#pragma unroll
    for (int i = 0; i < 4; i++) {
        const int r0 = bm + wm + i * 16 + g;
        const int r1 = r0 + 8;
#pragma unroll
        for (int j = 0; j < 4; j++) {
            const int cc = bn + wn + j * 8 + 2 * tig;
            float b0 = 0.f, b1 = 0.f;
            if (BIAS) { b0 = bias[cc]; b1 = bias[cc + 1]; }
            float2 v0, v1;
            v0.x = acc[i][j][0] + b0; v0.y = acc[i][j][1] + b1;
            v1.x = acc[i][j][2] + b0; v1.y = acc[i][j][3] + b1;
            if (ROUND) {
                v0.x = tf32r(v0.x); v0.y = tf32r(v0.y);
                v1.x = tf32r(v1.x); v1.y = tf32r(v1.y);
            }
            *(float2*)(Cb + (size_t)r0 * ldc + cc) = v0;
            *(float2*)(Cb + (size_t)r1 * ldc + cc) = v1;
        }
    }
}

// ---------------- softmax over rows of length 2048 (writes tf32) ------------
__global__ void softmax_kernel(float* __restrict__ Sc, float scale) {
    const size_t row = blockIdx.x;
    float* p = Sc + row * (size_t)cS;
    const int tid = threadIdx.x;
    __shared__ float smax[8];
    __shared__ float ssum[8];

    float v[8];
    float m = -CUDART_INF_F;
#pragma unroll
    for (int i = 0; i < 8; i++) {
        v[i] = p[tid + i * 256] * scale;
        m = fmaxf(m, v[i]);
    }
#pragma unroll
    for (int o = 16; o > 0; o >>= 1)
        m = fmaxf(m, __shfl_xor_sync(0xffffffffu, m, o));
    if ((tid & 31) == 0) smax[tid >> 5] = m;
    __syncthreads();
    m = smax[0];
#pragma unroll
    for (int wq = 1; wq < 8; wq++) m = fmaxf(m, smax[wq]);

    float s = 0.f;
#pragma unroll
    for (int i = 0; i < 8; i++) {
        v[i] = expf(v[i] - m);
        s += v[i];
    }
#pragma unroll
    for (int o = 16; o > 0; o >>= 1)
        s += __shfl_xor_sync(0xffffffffu, s, o);
    if ((tid & 31) == 0) ssum[tid >> 5] = s;
    __syncthreads();
    s = 0.f;
#pragma unroll
    for (int wq = 0; wq < 8; wq++) s += ssum[wq];
    const float inv = 1.0f / s;
#pragma unroll
    for (int i = 0; i < 8; i++) p[tid + i * 256] = tf32r(v[i] * inv);
}

// ---------------- launch ----------------------------------------------------
extern "C" void kernel_launch(void* const* d_in, const int* in_sizes, int n_in,
                              void* d_out, int out_size) {
    const float* query = (const float*)d_in[0];
    const float* key_  = (const float*)d_in[1];
    const float* value = (const float*)d_in[2];
    const float* Wq = (const float*)d_in[3];
    const float* bq = (const float*)d_in[4];
    const float* Wk = (const float*)d_in[5];
    const float* bk = (const float*)d_in[6];
    const float* Wv = (const float*)d_in[7];
    const float* bv = (const float*)d_in[8];
    const float* Wo = (const float*)d_in[9];
    const float* bo = (const float*)d_in[10];
    float* out = (float*)d_out;

    float *p_qrot, *p_krot, *p_vin, *p_wq, *p_wk, *p_wv, *p_wo;
    float *p_q, *p_k, *p_v, *p_vT, *p_s, *p_ctx;
    cudaGetSymbolAddress((void**)&p_qrot, g_qrot);
    cudaGetSymbolAddress((void**)&p_krot, g_krot);
    cudaGetSymbolAddress((void**)&p_vin, g_vin);
    cudaGetSymbolAddress((void**)&p_wq, g_wq);
    cudaGetSymbolAddress((void**)&p_wk, g_wk);
    cudaGetSymbolAddress((void**)&p_wv, g_wv);
    cudaGetSymbolAddress((void**)&p_wo, g_wo);
    cudaGetSymbolAddress((void**)&p_q, g_q);
    cudaGetSymbolAddress((void**)&p_k, g_k);
    cudaGetSymbolAddress((void**)&p_v, g_v);
    cudaGetSymbolAddress((void**)&p_vT, g_vT);
    cudaGetSymbolAddress((void**)&p_s, g_s);
    cudaGetSymbolAddress((void**)&p_ctx, g_ctx);

    const size_t SMEM = 4 * STAGE * sizeof(float);   // 73,728 B
    cudaFuncSetAttribute(gemm_tf32<true, true>,
                         cudaFuncAttributeMaxDynamicSharedMemorySize, (int)SMEM);
    cudaFuncSetAttribute(gemm_tf32<true, false>,
                         cudaFuncAttributeMaxDynamicSharedMemorySize, (int)SMEM);
    cudaFuncSetAttribute(gemm_tf32<false, false>,
                         cudaFuncAttributeMaxDynamicSharedMemorySize, (int)SMEM);
    cudaFuncSetAttribute(gemm_tf32<false, true>,
                         cudaFuncAttributeMaxDynamicSharedMemorySize, (int)SMEM);

    // 1) RoPE tables + apply (rounded)
    rope_tables_kernel<<<(cS * cH2 + 255) / 256, 256>>>();
    rope_apply_kernel<<<(int)((MH + 255) / 256), 256>>>(query, key_);

    // 2) prep: round weights + value to tf32
    round_copy_kernel<<<(int)(WN / 4 + 255) / 256, 256>>>(Wq, p_wq, WN / 4);
    round_copy_kernel<<<(int)(WN / 4 + 255) / 256, 256>>>(Wk, p_wk, WN / 4);
    round_copy_kernel<<<(int)(WN / 4 + 255) / 256, 256>>>(Wv, p_wv, WN / 4);
    round_copy_kernel<<<(int)(WN / 4 + 255) / 256, 256>>>(Wo, p_wo, WN / 4);
    round_copy_kernel<<<(int)(MH / 4 + 255) / 256, 256>>>(value, p_vin, MH / 4);

    // 3) projections (M=8192, N=K=2048): q,k rounded outputs; v plain
    dim3 gproj(cH / BN, cM / BM, 1);
    gemm_tf32<true, true><<<gproj, 256, SMEM>>>(p_qrot, p_wq, bq, p_q,
                                                cH, cH, cH, cH, cH, 0, 0, 0);
    gemm_tf32<true, true><<<gproj, 256, SMEM>>>(p_krot, p_wk, bk, p_k,
                                                cH, cH, cH, cH, cH, 0, 0, 0);
    gemm_tf32<true, false><<<gproj, 256, SMEM>>>(p_vin, p_wv, bv, p_v,
                                                 cH, cH, cH, cH, cH, 0, 0, 0);

    // 4) transpose v -> vT [H][M] (rounded)
    transpose_round_kernel<<<dim3(cH / 32, cM / 32), dim3(32, 8)>>>(p_v, p_vT);

    // 5) scores = q @ k^T (batched over B)
    dim3 gatt(cS / BN, cS / BM, cB);
    gemm_tf32<false, false><<<gatt, 256, SMEM>>>(p_q, p_k, nullptr, p_s,
                                                 cS, cH, cH, cH, cS, SH, SH, SS);

    // 6) softmax (rounded probs)
    const float scale = 1.0f / sqrtf((float)cH);
    softmax_kernel<<<cB * cS, 256>>>(p_s, scale);

    // 7) context = probs @ vT^T (batched): B operand vT row-stride cM
    gemm_tf32<false, true><<<gatt, 256, SMEM>>>(p_s, p_vT, nullptr, p_ctx,
                                                cH, cS, cS, cM, cH, SS, (size_t)cS, SH);

    // 8) out = ctx @ Wo^T + bo
    gemm_tf32<true, false><<<gproj, 256, SMEM>>>(p_ctx, p_wo, bo, out,
                                                 cH, cH, cH, cH, cH, 0, 0, 0);
}

// round 8
// speedup vs baseline: 3.5166x; 1.4178x over previous
#include <cuda_runtime.h>
#include <math.h>
#include <math_constants.h>
#include <stdint.h>

// Problem constants
constexpr int cB = 4;
constexpr int cS = 2048;
constexpr int cH = 2048;
constexpr int cH2 = cH / 2;
constexpr int cM = cB * cS;               // 8192
constexpr size_t SH = (size_t)cS * cH;
constexpr size_t SSz = (size_t)cS * cS;
constexpr size_t MHz = (size_t)cM * cH;
constexpr size_t WN = (size_t)cH * cH;

// ---------------- scratch ---------------------------------------------------
__device__ float g_cos[SH];
__device__ float g_sin[SH];
__device__ float g_qrot[MHz];
__device__ float g_krot[MHz];
__device__ float g_vin[MHz];
__device__ float g_wq[WN];
__device__ float g_wk[WN];
__device__ float g_wv[WN];
__device__ float g_wo[WN];
__device__ float g_q[MHz];
__device__ float g_k[MHz];
__device__ float g_v[MHz];
__device__ float g_vT[MHz];
__device__ float g_s[(size_t)cB * SSz];
__device__ float g_ctx[MHz];

// ---------------- helpers ---------------------------------------------------
__device__ __forceinline__ float tf32r(float x) {
    uint32_t u;
    asm("cvt.rna.tf32.f32 %0, %1;" : "=r"(u) : "f"(x));
    return __uint_as_float(u);
}

#define CPA16(smem_u32, gptr) \
    asm volatile("cp.async.cg.shared.global [%0], [%1], 16;" :: "r"(smem_u32), "l"(gptr))

#define LDSM4(r0, r1, r2, r3, a) \
    asm volatile("ldmatrix.sync.aligned.m8n8.x4.shared.b16 {%0,%1,%2,%3}, [%4];" \
                 : "=r"(r0), "=r"(r1), "=r"(r2), "=r"(r3) : "r"(a))

#define LDSM2(r0, r1, a) \
    asm volatile("ldmatrix.sync.aligned.m8n8.x2.shared.b16 {%0,%1}, [%2];" \
                 : "=r"(r0), "=r"(r1) : "r"(a))

// ---------------- RoPE tables ----------------------------------------------
__global__ void rope_tables_kernel() {
    int idx = blockIdx.x * blockDim.x + threadIdx.x;
    if (idx >= cS * cH2) return;
    int s = idx / cH2;
    int j = idx % cH2;
    float f = (float)pow(10000.0, -2.0 * (double)j / (double)cH);
    float ang = (float)s * f;
    float sn, cs;
    sincosf(ang, &sn, &cs);
    size_t base = (size_t)s * cH + j;
    g_cos[base] = cs; g_cos[base + cH2] = cs;
    g_sin[base] = sn; g_sin[base + cH2] = sn;
}

__global__ void rope_apply_kernel(const float* __restrict__ q,
                                  const float* __restrict__ k) {
    size_t idx = (size_t)blockIdx.x * blockDim.x + threadIdx.x;
    if (idx >= MHz) return;
    size_t sh = idx % SH;
    int h = (int)(idx % cH);
    float c = g_cos[sh];
    float s_ = g_sin[sh];
    float qv = q[idx];
    float kv = k[idx];
    float qr, kr;
    if (h < cH2) { qr = -q[idx + cH2]; kr = -k[idx + cH2]; }
    else         { qr =  q[idx - cH2]; kr =  k[idx - cH2]; }
    g_qrot[idx] = tf32r(qv * c + qr * s_);
    g_krot[idx] = tf32r(kv * c + kr * s_);
}

__global__ void round_copy_kernel(const float* __restrict__ in,
                                  float* __restrict__ out, size_t n4) {
    size_t i = (size_t)blockIdx.x * blockDim.x + threadIdx.x;
    if (i >= n4) return;
    float4 v = ((const float4*)in)[i];
    v.x = tf32r(v.x); v.y = tf32r(v.y); v.z = tf32r(v.z); v.w = tf32r(v.w);
    ((float4*)out)[i] = v;
}

__global__ void transpose_round_kernel(const float* __restrict__ in,
                                       float* __restrict__ out) {
    __shared__ float t[32][33];
    int x = blockIdx.x * 32 + threadIdx.x;
    int y0 = blockIdx.y * 32 + threadIdx.y;
#pragma unroll
    for (int j = 0; j < 32; j += 8)
        t[threadIdx.y + j][threadIdx.x] = in[(size_t)(y0 + j) * cH + x];
    __syncthreads();
    int ox = blockIdx.y * 32 + threadIdx.x;
    int oy = blockIdx.x * 32 + threadIdx.y;
#pragma unroll
    for (int j = 0; j < 32; j += 8)
        out[(size_t)(oy + j) * cM + ox] = tf32r(t[threadIdx.x][threadIdx.y + j]);
}

// ---------------- mma.sync TF32 GEMM (4-stage cp.async + ldmatrix) ----------
// C[m,n] = sum_k A[m,k] * B[n,k] (+bias[n]); A [M][K] K-major, B [N][K] K-major.
// Block 128x128x32, 256 threads (8 warps, 2x4 grid of 64x32 warp tiles).
// SMEM: SW128-swizzled 128B rows (BK=32 floats). 4 stages, wait_group 2,
// one __syncthreads per k-tile. Fragments via ldmatrix (tf32-as-b16 trick).
constexpr int BK = 32;
constexpr int TILE_B = 128 * BK * 4;          // 16384 bytes per matrix
constexpr int STG = 2 * TILE_B;               // 32768 bytes per stage (A+B)
constexpr int GEMM_SMEM = 4 * STG + 1024;     // +1024 for manual alignment

template<bool BIAS, bool ROUND>
__global__ __launch_bounds__(256)
void gemm_tc(const float* __restrict__ A, const float* __restrict__ Bm,
             const float* __restrict__ bias, float* __restrict__ C,
             int Kd, int lda, int ldb, int ldc,
             size_t strA, size_t strB, size_t strC) {
    extern __shared__ float smf[];
    uint32_t sbase = (uint32_t)__cvta_generic_to_shared(smf);
    sbase = (sbase + 1023u) & ~1023u;

    const int tid = threadIdx.x;
    const int lane = tid & 31;
    const int w = tid >> 5;
    const int wm = (w >> 2) * 64;
    const int wn = (w & 3) * 32;
    const int g = lane >> 2;
    const int tig = lane & 3;

    const float* Ab = A + blockIdx.z * strA;
    const float* Bb = Bm + blockIdx.z * strB;
    float* Cb = C + blockIdx.z * strC;
    const int bm = blockIdx.y * 128;
    const int bn = blockIdx.x * 128;
    const int nk = Kd / BK;

    // ---- loader precompute: 4 rows per thread per matrix (rows r0+32u) ----
    const int r0 = tid >> 3;
    const int ch = tid & 7;
    const uint32_t swoff = (uint32_t)((ch * 16) ^ ((r0 & 7) << 4));
    const uint32_t ldOffA = (uint32_t)(r0 * 128) + swoff;   // + u*4096 (+TILE_B for B)
    const float* gA0 = Ab + (size_t)(bm + r0) * lda + ch * 4;
    const float* gB0 = Bb + (size_t)(bn + r0) * ldb + ch * 4;
    const size_t gAs = 32 * (size_t)lda;
    const size_t gBs = 32 * (size_t)ldb;

    // ---- fragment address precompute (ldmatrix per-lane row addresses) ----
    // A: x4 covers m16xk8: matrices (rows g / g+8) x (k lo / k hi 16B)
    const int aRowOff = ((lane >> 3) & 1) * 8 + (lane & 7);
    const uint32_t aCS = (uint32_t)((lane >> 4) * 16);
    uint32_t aRB[4], aRX[4];
#pragma unroll
    for (int i = 0; i < 4; i++) {
        int row = wm + i * 16 + aRowOff;
        aRB[i] = (uint32_t)(row * 128);
        aRX[i] = (uint32_t)((row & 7) << 4);
    }
    // B: x2 covers n8xk8: matrices (k lo / k hi)
    const int bRowOff = lane & 7;
    const uint32_t bCS = (uint32_t)(((lane >> 3) & 1) * 16);
    uint32_t bRB[4], bRX[4];
#pragma unroll
    for (int j = 0; j < 4; j++) {
        int row = wn + j * 8 + bRowOff;
        bRB[j] = (uint32_t)(row * 128);
        bRX[j] = (uint32_t)((row & 7) << 4);
    }

    float acc[4][4][4];
#pragma unroll
    for (int i = 0; i < 4; i++)
#pragma unroll
        for (int j = 0; j < 4; j++)
#pragma unroll
            for (int r = 0; r < 4; r++) acc[i][j][r] = 0.f;

    // ---- prologue: prefetch stages 0..2 ----
#pragma unroll
    for (int t = 0; t < 3; t++) {
        const uint32_t ds = sbase + t * STG;
        const float* ga = gA0 + (size_t)t * BK;
        const float* gb = gB0 + (size_t)t * BK;
#pragma unroll
        for (int u = 0; u < 4; u++) {
            CPA16(ds + ldOffA + u * 4096, ga + u * gAs);
            CPA16(ds + TILE_B + ldOffA + u * 4096, gb + u * gBs);
        }
        asm volatile("cp.async.commit_group;");
    }

    // ---- mainloop ----
    for (int t = 0; t < nk; t++) {
        const int s = t & 3;
        asm volatile("cp.async.wait_group 2;");
        __syncthreads();

        if (t + 3 < nk) {
            const uint32_t ds = sbase + ((t + 3) & 3) * STG;
            const float* ga = gA0 + (size_t)(t + 3) * BK;
            const float* gb = gB0 + (size_t)(t + 3) * BK;
#pragma unroll
            for (int u = 0; u < 4; u++) {
                CPA16(ds + ldOffA + u * 4096, ga + u * gAs);
                CPA16(ds + TILE_B + ldOffA + u * 4096, gb + u * gBs);
            }
        }
        asm volatile("cp.async.commit_group;");

        const uint32_t aB = sbase + s * STG;
        const uint32_t bB = aB + TILE_B;
#pragma unroll
        for (int ks = 0; ks < 4; ks++) {
            const uint32_t kcol = (uint32_t)(ks * 32);
            uint32_t af[4][4];
#pragma unroll
            for (int i = 0; i < 4; i++)
                LDSM4(af[i][0], af[i][1], af[i][2], af[i][3],
                      aB + aRB[i] + ((kcol + aCS) ^ aRX[i]));
            uint32_t bf[4][2];
#pragma unroll
            for (int j = 0; j < 4; j++)
                LDSM2(bf[j][0], bf[j][1],
                      bB + bRB[j] + ((kcol + bCS) ^ bRX[j]));
#pragma unroll
            for (int i = 0; i < 4; i++)
#pragma unroll
                for (int j = 0; j < 4; j++) {
                    asm volatile(
                        "mma.sync.aligned.m16n8k8.row.col.f32.tf32.tf32.f32 "
                        "{%0,%1,%2,%3}, {%4,%5,%6,%7}, {%8,%9}, {%0,%1,%2,%3};"
                        : "+f"(acc[i][j][0]), "+f"(acc[i][j][1]),
                          "+f"(acc[i][j][2]), "+f"(acc[i][j][3])
                        : "r"(af[i][0]), "r"(af[i][1]), "r"(af[i][2]), "r"(af[i][3]),
                          "r"(bf[j][0]), "r"(bf[j][1]));
                }
        }
        __syncthreads();
    }

    // ---- epilogue ----
#pragma unroll
    for (int i = 0; i < 4; i++) {
        const int rr0 = bm + wm + i * 16 + g;
        const int rr1 = rr0 + 8;
#pragma unroll
        for (int j = 0; j < 4; j++) {
            const int cc = bn + wn + j * 8 + 2 * tig;
            float b0 = 0.f, b1 = 0.f;
            if (BIAS) { b0 = bias[cc]; b1 = bias[cc + 1]; }
            float2 v0, v1;
            v0.x = acc[i][j][0] + b0; v0.y = acc[i][j][1] + b1;
            v1.x = acc[i][j][2] + b0; v1.y = acc[i][j][3] + b1;
            if (ROUND) {
                v0.x = tf32r(v0.x); v0.y = tf32r(v0.y);
                v1.x = tf32r(v1.x); v1.y = tf32r(v1.y);
            }
            *(float2*)(Cb + (size_t)rr0 * ldc + cc) = v0;
            *(float2*)(Cb + (size_t)rr1 * ldc + cc) = v1;
        }
    }
}

// ---------------- softmax ---------------------------------------------------
__global__ void softmax_kernel(float* __restrict__ Sc, float scale) {
    const size_t row = blockIdx.x;
    float* p = Sc + row * (size_t)cS;
    const int tid = threadIdx.x;
    __shared__ float smax[8];
    __shared__ float ssum[8];

    float v[8];
    float m = -CUDART_INF_F;
#pragma unroll
    for (int i = 0; i < 8; i++) {
        v[i] = p[tid + i * 256] * scale;
        m = fmaxf(m, v[i]);
    }
#pragma unroll
    for (int o = 16; o > 0; o >>= 1)
        m = fmaxf(m, __shfl_xor_sync(0xffffffffu, m, o));
    if ((tid & 31) == 0) smax[tid >> 5] = m;
    __syncthreads();
    m = smax[0];
#pragma unroll
    for (int w = 1; w < 8; w++) m = fmaxf(m, smax[w]);

    float s = 0.f;
#pragma unroll
    for (int i = 0; i < 8; i++) {
        v[i] = expf(v[i] - m);
        s += v[i];
    }
#pragma unroll
    for (int o = 16; o > 0; o >>= 1)
        s += __shfl_xor_sync(0xffffffffu, s, o);
    if ((tid & 31) == 0) ssum[tid >> 5] = s;
    __syncthreads();
    s = 0.f;
#pragma unroll
    for (int w = 0; w < 8; w++) s += ssum[w];
    const float inv = 1.0f / s;
#pragma unroll
    for (int i = 0; i < 8; i++) p[tid + i * 256] = tf32r(v[i] * inv);
}

// ---------------- launch ----------------------------------------------------
extern "C" void kernel_launch(void* const* d_in, const int* in_sizes, int n_in,
                              void* d_out, int out_size) {
    const float* query = (const float*)d_in[0];
    const float* key_  = (const float*)d_in[1];
    const float* value = (const float*)d_in[2];
    const float* Wq = (const float*)d_in[3];
    const float* bq = (const float*)d_in[4];
    const float* Wk = (const float*)d_in[5];
    const float* bk = (const float*)d_in[6];
    const float* Wv = (const float*)d_in[7];
    const float* bv = (const float*)d_in[8];
    const float* Wo = (const float*)d_in[9];
    const float* bo = (const float*)d_in[10];
    float* out = (float*)d_out;

    float *p_qrot, *p_krot, *p_vin, *p_wq, *p_wk, *p_wv, *p_wo;
    float *p_q, *p_k, *p_v, *p_vT, *p_s, *p_ctx;
    cudaGetSymbolAddress((void**)&p_qrot, g_qrot);
    cudaGetSymbolAddress((void**)&p_krot, g_krot);
    cudaGetSymbolAddress((void**)&p_vin, g_vin);
    cudaGetSymbolAddress((void**)&p_wq, g_wq);
    cudaGetSymbolAddress((void**)&p_wk, g_wk);
    cudaGetSymbolAddress((void**)&p_wv, g_wv);
    cudaGetSymbolAddress((void**)&p_wo, g_wo);
    cudaGetSymbolAddress((void**)&p_q, g_q);
    cudaGetSymbolAddress((void**)&p_k, g_k);
    cudaGetSymbolAddress((void**)&p_v, g_v);
    cudaGetSymbolAddress((void**)&p_vT, g_vT);
    cudaGetSymbolAddress((void**)&p_s, g_s);
    cudaGetSymbolAddress((void**)&p_ctx, g_ctx);

    cudaFuncSetAttribute(gemm_tc<true, true>,
                         cudaFuncAttributeMaxDynamicSharedMemorySize, GEMM_SMEM);
    cudaFuncSetAttribute(gemm_tc<true, false>,
                         cudaFuncAttributeMaxDynamicSharedMemorySize, GEMM_SMEM);
    cudaFuncSetAttribute(gemm_tc<false, false>,
                         cudaFuncAttributeMaxDynamicSharedMemorySize, GEMM_SMEM);
    cudaFuncSetAttribute(gemm_tc<false, true>,
                         cudaFuncAttributeMaxDynamicSharedMemorySize, GEMM_SMEM);

    // 1) RoPE
    rope_tables_kernel<<<(cS * cH2 + 255) / 256, 256>>>();
    rope_apply_kernel<<<(int)((MHz + 255) / 256), 256>>>(query, key_);

    // 2) round weights + value to tf32
    round_copy_kernel<<<(int)(WN / 4 + 255) / 256, 256>>>(Wq, p_wq, WN / 4);
    round_copy_kernel<<<(int)(WN / 4 + 255) / 256, 256>>>(Wk, p_wk, WN / 4);
    round_copy_kernel<<<(int)(WN / 4 + 255) / 256, 256>>>(Wv, p_wv, WN / 4);
    round_copy_kernel<<<(int)(WN / 4 + 255) / 256, 256>>>(Wo, p_wo, WN / 4);
    round_copy_kernel<<<(int)(MHz / 4 + 255) / 256, 256>>>(value, p_vin, MHz / 4);

    // 3) projections (M=8192, N=K=2048)
    dim3 gproj(cH / 128, cM / 128, 1);
    gemm_tc<true, true><<<gproj, 256, GEMM_SMEM>>>(p_qrot, p_wq, bq, p_q,
                                                   cH, cH, cH, cH, 0, 0, 0);
    gemm_tc<true, true><<<gproj, 256, GEMM_SMEM>>>(p_krot, p_wk, bk, p_k,
                                                   cH, cH, cH, cH, 0, 0, 0);
    gemm_tc<true, false><<<gproj, 256, GEMM_SMEM>>>(p_vin, p_wv, bv, p_v,
                                                    cH, cH, cH, cH, 0, 0, 0);

    // 4) transpose v -> vT [H][M]
    transpose_round_kernel<<<dim3(cH / 32, cM / 32), dim3(32, 8)>>>(p_v, p_vT);

    // 5) scores = q @ k^T (batched)
    dim3 gatt(cS / 128, cS / 128, cB);
    gemm_tc<false, false><<<gatt, 256, GEMM_SMEM>>>(p_q, p_k, nullptr, p_s,
                                                    cH, cH, cH, cS, SH, SH, SSz);

    // 6) softmax
    const float scale = 1.0f / sqrtf((float)cH);
    softmax_kernel<<<cB * cS, 256>>>(p_s, scale);

    // 7) context = probs @ vT^T (batched)
    gemm_tc<false, true><<<gatt, 256, GEMM_SMEM>>>(p_s, p_vT, nullptr, p_ctx,
                                                   cS, cS, cM, cH, SSz, (size_t)cS, SH);

    // 8) out = ctx @ Wo^T + bo
    gemm_tc<true, false><<<gproj, 256, GEMM_SMEM>>>(p_ctx, p_wo, bo, out,
                                                    cH, cH, cH, cH, 0, 0, 0);
}

// round 9
// speedup vs baseline: 4.2526x; 1.2093x over previous
#include <cuda_runtime.h>
#include <math.h>
#include <math_constants.h>
#include <stdint.h>

// Problem constants
constexpr int cB = 4;
constexpr int cS = 2048;
constexpr int cH = 2048;
constexpr int cH2 = cH / 2;
constexpr int cM = cB * cS;               // 8192
constexpr size_t SH = (size_t)cS * cH;
constexpr size_t SSz = (size_t)cS * cS;
constexpr size_t MHz = (size_t)cM * cH;
constexpr size_t WN = (size_t)cH * cH;

// ---------------- scratch ---------------------------------------------------
__device__ float g_cos[SH];
__device__ float g_sin[SH];
__device__ float g_qrot[MHz];
__device__ float g_krot[MHz];
__device__ float g_vin[MHz];
__device__ float g_wq[WN];
__device__ float g_wk[WN];
__device__ float g_wv[WN];
__device__ float g_wo[WN];
__device__ float g_q[MHz];
__device__ float g_k[MHz];
__device__ float g_v[MHz];
__device__ float g_vT[MHz];
__device__ float g_s[(size_t)cB * SSz];
__device__ float g_ctx[MHz];

// ---------------- helpers ---------------------------------------------------
__device__ __forceinline__ float tf32r(float x) {
    uint32_t u;
    asm("cvt.rna.tf32.f32 %0, %1;" : "=r"(u) : "f"(x));
    return __uint_as_float(u);
}

#define CPA16(smem_u32, gptr) \
    asm volatile("cp.async.cg.shared.global [%0], [%1], 16;" :: "r"(smem_u32), "l"(gptr))

#define LDSM4(r0, r1, r2, r3, a) \
    asm volatile("ldmatrix.sync.aligned.m8n8.x4.shared.b16 {%0,%1,%2,%3}, [%4];" \
                 : "=r"(r0), "=r"(r1), "=r"(r2), "=r"(r3) : "r"(a))

#define LDSM2(r0, r1, a) \
    asm volatile("ldmatrix.sync.aligned.m8n8.x2.shared.b16 {%0,%1}, [%2];" \
                 : "=r"(r0), "=r"(r1) : "r"(a))

// ---------------- RoPE tables ----------------------------------------------
__global__ void rope_tables_kernel() {
    int idx = blockIdx.x * blockDim.x + threadIdx.x;
    if (idx >= cS * cH2) return;
    int s = idx / cH2;
    int j = idx % cH2;
    float f = (float)pow(10000.0, -2.0 * (double)j / (double)cH);
    float ang = (float)s * f;
    float sn, cs;
    sincosf(ang, &sn, &cs);
    size_t base = (size_t)s * cH + j;
    g_cos[base] = cs; g_cos[base + cH2] = cs;
    g_sin[base] = sn; g_sin[base + cH2] = sn;
}

__global__ void rope_apply_kernel(const float* __restrict__ q,
                                  const float* __restrict__ k) {
    size_t idx = (size_t)blockIdx.x * blockDim.x + threadIdx.x;
    if (idx >= MHz) return;
    size_t sh = idx % SH;
    int h = (int)(idx % cH);
    float c = g_cos[sh];
    float s_ = g_sin[sh];
    float qv = q[idx];
    float kv = k[idx];
    float qr, kr;
    if (h < cH2) { qr = -q[idx + cH2]; kr = -k[idx + cH2]; }
    else         { qr =  q[idx - cH2]; kr =  k[idx - cH2]; }
    g_qrot[idx] = tf32r(qv * c + qr * s_);
    g_krot[idx] = tf32r(kv * c + kr * s_);
}

__global__ void round_copy_kernel(const float* __restrict__ in,
                                  float* __restrict__ out, size_t n4) {
    size_t i = (size_t)blockIdx.x * blockDim.x + threadIdx.x;
    if (i >= n4) return;
    float4 v = ((const float4*)in)[i];
    v.x = tf32r(v.x); v.y = tf32r(v.y); v.z = tf32r(v.z); v.w = tf32r(v.w);
    ((float4*)out)[i] = v;
}

__global__ void transpose_round_kernel(const float* __restrict__ in,
                                       float* __restrict__ out) {
    __shared__ float t[32][33];
    int x = blockIdx.x * 32 + threadIdx.x;
    int y0 = blockIdx.y * 32 + threadIdx.y;
#pragma unroll
    for (int j = 0; j < 32; j += 8)
        t[threadIdx.y + j][threadIdx.x] = in[(size_t)(y0 + j) * cH + x];
    __syncthreads();
    int ox = blockIdx.y * 32 + threadIdx.x;
    int oy = blockIdx.x * 32 + threadIdx.y;
#pragma unroll
    for (int j = 0; j < 32; j += 8)
        out[(size_t)(oy + j) * cM + ox] = tf32r(t[threadIdx.x][threadIdx.y + j]);
}

// ---------------- mma.sync TF32 GEMM (3-stage cp.async + ldmatrix, occ 2) ---
// C[m,n] = sum_k A[m,k] * B[n,k] (+bias[n]); A [M][K] K-major, B [N][K] K-major.
// Block 128x128x32, 256 threads (8 warps, 2x4 grid of 64x32 warp tiles).
// SMEM: SW128-swizzled 128B rows. 3 stages (97KB) so 2 CTAs fit per SM.
constexpr int BK = 32;
constexpr int TILE_B = 128 * BK * 4;          // 16384 bytes per matrix
constexpr int STG = 2 * TILE_B;               // 32768 bytes per stage (A+B)
constexpr int NSTG = 3;
constexpr int GEMM_SMEM = NSTG * STG + 1024;  // 99328 (x2 CTA = 198656 < 228KB)

template<bool BIAS, bool ROUND>
__global__ __launch_bounds__(256, 2)
void gemm_tc(const float* __restrict__ A, const float* __restrict__ Bm,
             const float* __restrict__ bias, float* __restrict__ C,
             int Kd, int lda, int ldb, int ldc,
             size_t strA, size_t strB, size_t strC) {
    extern __shared__ float smf[];
    uint32_t sbase = (uint32_t)__cvta_generic_to_shared(smf);
    sbase = (sbase + 1023u) & ~1023u;

    const int tid = threadIdx.x;
    const int lane = tid & 31;
    const int w = tid >> 5;
    const int wm = (w >> 2) * 64;
    const int wn = (w & 3) * 32;
    const int g = lane >> 2;
    const int tig = lane & 3;

    const float* Ab = A + blockIdx.z * strA;
    const float* Bb = Bm + blockIdx.z * strB;
    float* Cb = C + blockIdx.z * strC;
    const int bm = blockIdx.y * 128;
    const int bn = blockIdx.x * 128;
    const int nk = Kd / BK;

    // ---- loader precompute: 4 rows per thread per matrix (rows r0+32u) ----
    const int r0 = tid >> 3;
    const int ch = tid & 7;
    const uint32_t swoff = (uint32_t)((ch * 16) ^ ((r0 & 7) << 4));
    const uint32_t ldOffA = (uint32_t)(r0 * 128) + swoff;
    const float* gA0 = Ab + (size_t)(bm + r0) * lda + ch * 4;
    const float* gB0 = Bb + (size_t)(bn + r0) * ldb + ch * 4;
    const size_t gAs = 32 * (size_t)lda;
    const size_t gBs = 32 * (size_t)ldb;

    // ---- fragment address precompute ----
    const int aRowOff = ((lane >> 3) & 1) * 8 + (lane & 7);
    const uint32_t aCS = (uint32_t)((lane >> 4) * 16);
    uint32_t aRB[4], aRX[4];
#pragma unroll
    for (int i = 0; i < 4; i++) {
        int row = wm + i * 16 + aRowOff;
        aRB[i] = (uint32_t)(row * 128);
        aRX[i] = (uint32_t)((row & 7) << 4);
    }
    const int bRowOff = lane & 7;
    const uint32_t bCS = (uint32_t)(((lane >> 3) & 1) * 16);
    uint32_t bRB[4], bRX[4];
#pragma unroll
    for (int j = 0; j < 4; j++) {
        int row = wn + j * 8 + bRowOff;
        bRB[j] = (uint32_t)(row * 128);
        bRX[j] = (uint32_t)((row & 7) << 4);
    }

    float acc[4][4][4];
#pragma unroll
    for (int i = 0; i < 4; i++)
#pragma unroll
        for (int j = 0; j < 4; j++)
#pragma unroll
            for (int r = 0; r < 4; r++) acc[i][j][r] = 0.f;

    // ---- prologue: prefetch stages 0..1 ----
#pragma unroll
    for (int t = 0; t < 2; t++) {
        const uint32_t ds = sbase + t * STG;
        const float* ga = gA0 + (size_t)t * BK;
        const float* gb = gB0 + (size_t)t * BK;
#pragma unroll
        for (int u = 0; u < 4; u++) {
            CPA16(ds + ldOffA + u * 4096, ga + u * gAs);
            CPA16(ds + TILE_B + ldOffA + u * 4096, gb + u * gBs);
        }
        asm volatile("cp.async.commit_group;");
    }

    // ---- mainloop ----
    int s = 0, sp = 2;   // current stage, prefetch stage
    for (int t = 0; t < nk; t++) {
        asm volatile("cp.async.wait_group 1;");
        __syncthreads();

        if (t + 2 < nk) {
            const uint32_t ds = sbase + sp * STG;
            const float* ga = gA0 + (size_t)(t + 2) * BK;
            const float* gb = gB0 + (size_t)(t + 2) * BK;
#pragma unroll
            for (int u = 0; u < 4; u++) {
                CPA16(ds + ldOffA + u * 4096, ga + u * gAs);
                CPA16(ds + TILE_B + ldOffA + u * 4096, gb + u * gBs);
            }
        }
        asm volatile("cp.async.commit_group;");

        const uint32_t aB = sbase + s * STG;
        const uint32_t bB = aB + TILE_B;
#pragma unroll
        for (int ks = 0; ks < 4; ks++) {
            const uint32_t kcol = (uint32_t)(ks * 32);
            uint32_t af[4][4];
#pragma unroll
            for (int i = 0; i < 4; i++)
                LDSM4(af[i][0], af[i][1], af[i][2], af[i][3],
                      aB + aRB[i] + ((kcol + aCS) ^ aRX[i]));
            uint32_t bf[4][2];
#pragma unroll
            for (int j = 0; j < 4; j++)
                LDSM2(bf[j][0], bf[j][1],
                      bB + bRB[j] + ((kcol + bCS) ^ bRX[j]));
#pragma unroll
            for (int i = 0; i < 4; i++)
#pragma unroll
                for (int j = 0; j < 4; j++) {
                    asm volatile(
                        "mma.sync.aligned.m16n8k8.row.col.f32.tf32.tf32.f32 "
                        "{%0,%1,%2,%3}, {%4,%5,%6,%7}, {%8,%9}, {%0,%1,%2,%3};"
                        : "+f"(acc[i][j][0]), "+f"(acc[i][j][1]),
                          "+f"(acc[i][j][2]), "+f"(acc[i][j][3])
                        : "r"(af[i][0]), "r"(af[i][1]), "r"(af[i][2]), "r"(af[i][3]),
                          "r"(bf[j][0]), "r"(bf[j][1]));
                }
        }
        __syncthreads();
        s = (s == NSTG - 1) ? 0 : s + 1;
        sp = (sp == NSTG - 1) ? 0 : sp + 1;
    }

    // ---- epilogue ----
#pragma unroll
    for (int i = 0; i < 4; i++) {
        const int rr0 = bm + wm + i * 16 + g;
        const int rr1 = rr0 + 8;
#pragma unroll
        for (int j = 0; j < 4; j++) {
            const int cc = bn + wn + j * 8 + 2 * tig;
            float b0 = 0.f, b1 = 0.f;
            if (BIAS) { b0 = bias[cc]; b1 = bias[cc + 1]; }
            float2 v0, v1;
            v0.x = acc[i][j][0] + b0; v0.y = acc[i][j][1] + b1;
            v1.x = acc[i][j][2] + b0; v1.y = acc[i][j][3] + b1;
            if (ROUND) {
                v0.x = tf32r(v0.x); v0.y = tf32r(v0.y);
                v1.x = tf32r(v1.x); v1.y = tf32r(v1.y);
            }
            *(float2*)(Cb + (size_t)rr0 * ldc + cc) = v0;
            *(float2*)(Cb + (size_t)rr1 * ldc + cc) = v1;
        }
    }
}

// ---------------- softmax ---------------------------------------------------
__global__ void softmax_kernel(float* __restrict__ Sc, float scale) {
    const size_t row = blockIdx.x;
    float* p = Sc + row * (size_t)cS;
    const int tid = threadIdx.x;
    __shared__ float smax[8];
    __shared__ float ssum[8];

    float v[8];
    float m = -CUDART_INF_F;
#pragma unroll
    for (int i = 0; i < 8; i++) {
        v[i] = p[tid + i * 256] * scale;
        m = fmaxf(m, v[i]);
    }
#pragma unroll
    for (int o = 16; o > 0; o >>= 1)
        m = fmaxf(m, __shfl_xor_sync(0xffffffffu, m, o));
    if ((tid & 31) == 0) smax[tid >> 5] = m;
    __syncthreads();
    m = smax[0];
#pragma unroll
    for (int w = 1; w < 8; w++) m = fmaxf(m, smax[w]);

    float s = 0.f;
#pragma unroll
    for (int i = 0; i < 8; i++) {
        v[i] = expf(v[i] - m);
        s += v[i];
    }
#pragma unroll
    for (int o = 16; o > 0; o >>= 1)
        s += __shfl_xor_sync(0xffffffffu, s, o);
    if ((tid & 31) == 0) ssum[tid >> 5] = s;
    __syncthreads();
    s = 0.f;
#pragma unroll
    for (int w = 0; w < 8; w++) s += ssum[w];
    const float inv = 1.0f / s;
#pragma unroll
    for (int i = 0; i < 8; i++) p[tid + i * 256] = tf32r(v[i] * inv);
}

// ---------------- launch ----------------------------------------------------
extern "C" void kernel_launch(void* const* d_in, const int* in_sizes, int n_in,
                              void* d_out, int out_size) {
    const float* query = (const float*)d_in[0];
    const float* key_  = (const float*)d_in[1];
    const float* value = (const float*)d_in[2];
    const float* Wq = (const float*)d_in[3];
    const float* bq = (const float*)d_in[4];
    const float* Wk = (const float*)d_in[5];
    const float* bk = (const float*)d_in[6];
    const float* Wv = (const float*)d_in[7];
    const float* bv = (const float*)d_in[8];
    const float* Wo = (const float*)d_in[9];
    const float* bo = (const float*)d_in[10];
    float* out = (float*)d_out;

    float *p_qrot, *p_krot, *p_vin, *p_wq, *p_wk, *p_wv, *p_wo;
    float *p_q, *p_k, *p_v, *p_vT, *p_s, *p_ctx;
    cudaGetSymbolAddress((void**)&p_qrot, g_qrot);
    cudaGetSymbolAddress((void**)&p_krot, g_krot);
    cudaGetSymbolAddress((void**)&p_vin, g_vin);
    cudaGetSymbolAddress((void**)&p_wq, g_wq);
    cudaGetSymbolAddress((void**)&p_wk, g_wk);
    cudaGetSymbolAddress((void**)&p_wv, g_wv);
    cudaGetSymbolAddress((void**)&p_wo, g_wo);
    cudaGetSymbolAddress((void**)&p_q, g_q);
    cudaGetSymbolAddress((void**)&p_k, g_k);
    cudaGetSymbolAddress((void**)&p_v, g_v);
    cudaGetSymbolAddress((void**)&p_vT, g_vT);
    cudaGetSymbolAddress((void**)&p_s, g_s);
    cudaGetSymbolAddress((void**)&p_ctx, g_ctx);

    cudaFuncSetAttribute(gemm_tc<true, true>,
                         cudaFuncAttributeMaxDynamicSharedMemorySize, GEMM_SMEM);
    cudaFuncSetAttribute(gemm_tc<true, false>,
                         cudaFuncAttributeMaxDynamicSharedMemorySize, GEMM_SMEM);
    cudaFuncSetAttribute(gemm_tc<false, false>,
                         cudaFuncAttributeMaxDynamicSharedMemorySize, GEMM_SMEM);
    cudaFuncSetAttribute(gemm_tc<false, true>,
                         cudaFuncAttributeMaxDynamicSharedMemorySize, GEMM_SMEM);

    // Launch order arranged so launch #6 (ncu -s 5 -c 1) is a projection GEMM.
    // 1) RoPE
    rope_tables_kernel<<<(cS * cH2 + 255) / 256, 256>>>();                       // 1
    rope_apply_kernel<<<(int)((MHz + 255) / 256), 256>>>(query, key_);           // 2

    // 2) rounding prep (partial, enough for gemm q)
    round_copy_kernel<<<(int)(MHz / 4 + 255) / 256, 256>>>(value, p_vin, MHz / 4); // 3
    round_copy_kernel<<<(int)(WN / 4 + 255) / 256, 256>>>(Wq, p_wq, WN / 4);       // 4
    round_copy_kernel<<<(int)(WN / 4 + 255) / 256, 256>>>(Wk, p_wk, WN / 4);       // 5

    // 3) projections (M=8192, N=K=2048)
    dim3 gproj(cH / 128, cM / 128, 1);
    gemm_tc<true, true><<<gproj, 256, GEMM_SMEM>>>(p_qrot, p_wq, bq, p_q,
                                                   cH, cH, cH, cH, 0, 0, 0);     // 6 <- profiled
    round_copy_kernel<<<(int)(WN / 4 + 255) / 256, 256>>>(Wv, p_wv, WN / 4);     // 7
    round_copy_kernel<<<(int)(WN / 4 + 255) / 256, 256>>>(Wo, p_wo, WN / 4);     // 8
    gemm_tc<true, true><<<gproj, 256, GEMM_SMEM>>>(p_krot, p_wk, bk, p_k,
                                                   cH, cH, cH, cH, 0, 0, 0);
    gemm_tc<true, false><<<gproj, 256, GEMM_SMEM>>>(p_vin, p_wv, bv, p_v,
                                                    cH, cH, cH, cH, 0, 0, 0);

    // 4) transpose v -> vT [H][M]
    transpose_round_kernel<<<dim3(cH / 32, cM / 32), dim3(32, 8)>>>(p_v, p_vT);

    // 5) scores = q @ k^T (batched)
    dim3 gatt(cS / 128, cS / 128, cB);
    gemm_tc<false, false><<<gatt, 256, GEMM_SMEM>>>(p_q, p_k, nullptr, p_s,
                                                    cH, cH, cH, cS, SH, SH, SSz);

    // 6) softmax
    const float scale = 1.0f / sqrtf((float)cH);
    softmax_kernel<<<cB * cS, 256>>>(p_s, scale);

    // 7) context = probs @ vT^T (batched)
    gemm_tc<false, true><<<gatt, 256, GEMM_SMEM>>>(p_s, p_vT, nullptr, p_ctx,
                                                   cS, cS, cM, cH, SSz, (size_t)cS, SH);

    // 8) out = ctx @ Wo^T + bo
    gemm_tc<true, false><<<gproj, 256, GEMM_SMEM>>>(p_ctx, p_wo, bo, out,
                                                    cH, cH, cH, cH, 0, 0, 0);
}

// round 10
// speedup vs baseline: 4.3376x; 1.0200x over previous
#include <cuda_runtime.h>
#include <math.h>
#include <math_constants.h>
#include <stdint.h>

// Problem constants
constexpr int cB = 4;
constexpr int cS = 2048;
constexpr int cH = 2048;
constexpr int cH2 = cH / 2;
constexpr int cM = cB * cS;               // 8192
constexpr size_t SH = (size_t)cS * cH;
constexpr size_t SSz = (size_t)cS * cS;
constexpr size_t MHz = (size_t)cM * cH;
constexpr size_t WN = (size_t)cH * cH;

// ---------------- scratch ---------------------------------------------------
__device__ float g_cos[SH];
__device__ float g_sin[SH];
__device__ float g_qrot[MHz];
__device__ float g_krot[MHz];
__device__ float g_vin[MHz];
__device__ float g_wq[WN];
__device__ float g_wk[WN];
__device__ float g_wv[WN];
__device__ float g_wo[WN];
__device__ float g_q[MHz];
__device__ float g_k[MHz];
__device__ float g_v[MHz];
__device__ float g_vT[MHz];
__device__ float g_s[(size_t)cB * SSz];
__device__ float g_ctx[MHz];

// ---------------- helpers ---------------------------------------------------
__device__ __forceinline__ float tf32r(float x) {
    uint32_t u;
    asm("cvt.rna.tf32.f32 %0, %1;" : "=r"(u) : "f"(x));
    return __uint_as_float(u);
}

#define CPA16(smem_u32, gptr) \
    asm volatile("cp.async.cg.shared.global [%0], [%1], 16;" :: "r"(smem_u32), "l"(gptr))

#define LDSM4(r0, r1, r2, r3, a) \
    asm volatile("ldmatrix.sync.aligned.m8n8.x4.shared.b16 {%0,%1,%2,%3}, [%4];" \
                 : "=r"(r0), "=r"(r1), "=r"(r2), "=r"(r3) : "r"(a))

#define LDSM2(r0, r1, a) \
    asm volatile("ldmatrix.sync.aligned.m8n8.x2.shared.b16 {%0,%1}, [%2];" \
                 : "=r"(r0), "=r"(r1) : "r"(a))

// ---------------- RoPE tables ----------------------------------------------
__global__ void rope_tables_kernel() {
    int idx = blockIdx.x * blockDim.x + threadIdx.x;
    if (idx >= cS * cH2) return;
    int s = idx / cH2;
    int j = idx % cH2;
    float f = (float)pow(10000.0, -2.0 * (double)j / (double)cH);
    float ang = (float)s * f;
    float sn, cs;
    sincosf(ang, &sn, &cs);
    size_t base = (size_t)s * cH + j;
    g_cos[base] = cs; g_cos[base + cH2] = cs;
    g_sin[base] = sn; g_sin[base + cH2] = sn;
}

// RoPE on q,k + tf32-round value, one pass over MHz
__global__ void rope_apply_v_kernel(const float* __restrict__ q,
                                    const float* __restrict__ k,
                                    const float* __restrict__ v) {
    size_t idx = (size_t)blockIdx.x * blockDim.x + threadIdx.x;
    if (idx >= MHz) return;
    size_t sh = idx % SH;
    int h = (int)(idx % cH);
    float c = g_cos[sh];
    float s_ = g_sin[sh];
    float qv = q[idx];
    float kv = k[idx];
    float qr, kr;
    if (h < cH2) { qr = -q[idx + cH2]; kr = -k[idx + cH2]; }
    else         { qr =  q[idx - cH2]; kr =  k[idx - cH2]; }
    g_qrot[idx] = tf32r(qv * c + qr * s_);
    g_krot[idx] = tf32r(kv * c + kr * s_);
    g_vin[idx]  = tf32r(v[idx]);
}

// round all 4 weight matrices: grid (WN/4/256, 4)
__global__ void round_weights_kernel(const float* __restrict__ w0,
                                     const float* __restrict__ w1,
                                     const float* __restrict__ w2,
                                     const float* __restrict__ w3) {
    const float* src = (blockIdx.y == 0) ? w0 : (blockIdx.y == 1) ? w1
                     : (blockIdx.y == 2) ? w2 : w3;
    float* dst = (blockIdx.y == 0) ? g_wq : (blockIdx.y == 1) ? g_wk
               : (blockIdx.y == 2) ? g_wv : g_wo;
    size_t i = (size_t)blockIdx.x * blockDim.x + threadIdx.x;
    float4 v = ((const float4*)src)[i];
    v.x = tf32r(v.x); v.y = tf32r(v.y); v.z = tf32r(v.z); v.w = tf32r(v.w);
    ((float4*)dst)[i] = v;
}

__global__ void transpose_round_kernel(const float* __restrict__ in,
                                       float* __restrict__ out) {
    __shared__ float t[32][33];
    int x = blockIdx.x * 32 + threadIdx.x;
    int y0 = blockIdx.y * 32 + threadIdx.y;
#pragma unroll
    for (int j = 0; j < 32; j += 8)
        t[threadIdx.y + j][threadIdx.x] = in[(size_t)(y0 + j) * cH + x];
    __syncthreads();
    int ox = blockIdx.y * 32 + threadIdx.x;
    int oy = blockIdx.x * 32 + threadIdx.y;
#pragma unroll
    for (int j = 0; j < 32; j += 8)
        out[(size_t)(oy + j) * cM + ox] = tf32r(t[threadIdx.x][threadIdx.y + j]);
}

// ---------------- mma.sync TF32 GEMM core -----------------------------------
// C[m,n] = sum_k A[m,k] * B[n,k] (+bias[n] if bias); B [N][K] K-major.
// Block 128x128x32, 256 threads, 3-stage cp.async, ldmatrix frags,
// ONE barrier per k-tile (bottom barrier proved redundant with 3 stages).
constexpr int BK = 32;
constexpr int TILE_B = 128 * BK * 4;          // 16384 bytes per matrix
constexpr int STG = 2 * TILE_B;               // 32768 bytes per stage
constexpr int NSTG = 3;
constexpr int GEMM_SMEM = NSTG * STG + 1024;  // 99328 (2 CTA/SM fits in 228KB)

__device__ __forceinline__ void gemm_core(
    const float* __restrict__ Ab, const float* __restrict__ Bb,
    const float* __restrict__ bias, float* __restrict__ Cb,
    int Kd, int lda, int ldb, int ldc, int bm, int bn, bool round_out) {
    extern __shared__ float smf[];
    uint32_t sbase = (uint32_t)__cvta_generic_to_shared(smf);
    sbase = (sbase + 1023u) & ~1023u;

    const int tid = threadIdx.x;
    const int lane = tid & 31;
    const int w = tid >> 5;
    const int wm = (w >> 2) * 64;
    const int wn = (w & 3) * 32;
    const int g = lane >> 2;
    const int tig = lane & 3;
    const int nk = Kd / BK;

    // loaders: 4 rows/thread/matrix
    const int r0 = tid >> 3;
    const int ch = tid & 7;
    const uint32_t swoff = (uint32_t)((ch * 16) ^ ((r0 & 7) << 4));
    const uint32_t ldOffA = (uint32_t)(r0 * 128) + swoff;
    const float* gA0 = Ab + (size_t)(bm + r0) * lda + ch * 4;
    const float* gB0 = Bb + (size_t)(bn + r0) * ldb + ch * 4;
    const size_t gAs = 32 * (size_t)lda;
    const size_t gBs = 32 * (size_t)ldb;

    // fragment addresses
    const int aRowOff = ((lane >> 3) & 1) * 8 + (lane & 7);
    const uint32_t aCS = (uint32_t)((lane >> 4) * 16);
    uint32_t aRB[4], aRX[4];
#pragma unroll
    for (int i = 0; i < 4; i++) {
        int row = wm + i * 16 + aRowOff;
        aRB[i] = (uint32_t)(row * 128);
        aRX[i] = (uint32_t)((row & 7) << 4);
    }
    const int bRowOff = lane & 7;
    const uint32_t bCS = (uint32_t)(((lane >> 3) & 1) * 16);
    uint32_t bRB[4], bRX[4];
#pragma unroll
    for (int j = 0; j < 4; j++) {
        int row = wn + j * 8 + bRowOff;
        bRB[j] = (uint32_t)(row * 128);
        bRX[j] = (uint32_t)((row & 7) << 4);
    }

    float acc[4][4][4];
#pragma unroll
    for (int i = 0; i < 4; i++)
#pragma unroll
        for (int j = 0; j < 4; j++)
#pragma unroll
            for (int r = 0; r < 4; r++) acc[i][j][r] = 0.f;

    // prologue: stages 0,1
#pragma unroll
    for (int t = 0; t < 2; t++) {
        const uint32_t ds = sbase + t * STG;
        const float* ga = gA0 + (size_t)t * BK;
        const float* gb = gB0 + (size_t)t * BK;
#pragma unroll
        for (int u = 0; u < 4; u++) {
            CPA16(ds + ldOffA + u * 4096, ga + u * gAs);
            CPA16(ds + TILE_B + ldOffA + u * 4096, gb + u * gBs);
        }
        asm volatile("cp.async.commit_group;");
    }

    int s = 0, sp = 2;
    for (int t = 0; t < nk; t++) {
        asm volatile("cp.async.wait_group 1;");
        __syncthreads();   // single barrier per k-tile

        if (t + 2 < nk) {
            const uint32_t ds = sbase + sp * STG;
            const float* ga = gA0 + (size_t)(t + 2) * BK;
            const float* gb = gB0 + (size_t)(t + 2) * BK;
#pragma unroll
            for (int u = 0; u < 4; u++) {
                CPA16(ds + ldOffA + u * 4096, ga + u * gAs);
                CPA16(ds + TILE_B + ldOffA + u * 4096, gb + u * gBs);
            }
        }
        asm volatile("cp.async.commit_group;");

        const uint32_t aB = sbase + s * STG;
        const uint32_t bB = aB + TILE_B;
#pragma unroll
        for (int ks = 0; ks < 4; ks++) {
            const uint32_t kcol = (uint32_t)(ks * 32);
            uint32_t af[4][4];
#pragma unroll
            for (int i = 0; i < 4; i++)
                LDSM4(af[i][0], af[i][1], af[i][2], af[i][3],
                      aB + aRB[i] + ((kcol + aCS) ^ aRX[i]));
            uint32_t bf[4][2];
#pragma unroll
            for (int j = 0; j < 4; j++)
                LDSM2(bf[j][0], bf[j][1],
                      bB + bRB[j] + ((kcol + bCS) ^ bRX[j]));
#pragma unroll
            for (int i = 0; i < 4; i++)
#pragma unroll
                for (int j = 0; j < 4; j++) {
                    asm volatile(
                        "mma.sync.aligned.m16n8k8.row.col.f32.tf32.tf32.f32 "
                        "{%0,%1,%2,%3}, {%4,%5,%6,%7}, {%8,%9}, {%0,%1,%2,%3};"
                        : "+f"(acc[i][j][0]), "+f"(acc[i][j][1]),
                          "+f"(acc[i][j][2]), "+f"(acc[i][j][3])
                        : "r"(af[i][0]), "r"(af[i][1]), "r"(af[i][2]), "r"(af[i][3]),
                          "r"(bf[j][0]), "r"(bf[j][1]));
                }
        }
        s = (s == NSTG - 1) ? 0 : s + 1;
        sp = (sp == NSTG - 1) ? 0 : sp + 1;
    }

    // epilogue
#pragma unroll
    for (int i = 0; i < 4; i++) {
        const int rr0 = bm + wm + i * 16 + g;
        const int rr1 = rr0 + 8;
#pragma unroll
        for (int j = 0; j < 4; j++) {
            const int cc = bn + wn + j * 8 + 2 * tig;
            float b0 = 0.f, b1 = 0.f;
            if (bias) { b0 = bias[cc]; b1 = bias[cc + 1]; }
            float2 v0, v1;
            v0.x = acc[i][j][0] + b0; v0.y = acc[i][j][1] + b1;
            v1.x = acc[i][j][2] + b0; v1.y = acc[i][j][3] + b1;
            if (round_out) {
                v0.x = tf32r(v0.x); v0.y = tf32r(v0.y);
                v1.x = tf32r(v1.x); v1.y = tf32r(v1.y);
            }
            *(float2*)(Cb + (size_t)rr0 * ldc + cc) = v0;
            *(float2*)(Cb + (size_t)rr1 * ldc + cc) = v1;
        }
    }
}

// fused q/k/v projections: grid (16, 64, 3); z selects operands
__global__ __launch_bounds__(256, 2)
void gemm3_proj(const float* __restrict__ bq, const float* __restrict__ bk,
                const float* __restrict__ bv) {
    const int z = blockIdx.z;
    const float* A = (z == 0) ? g_qrot : (z == 1) ? g_krot : g_vin;
    const float* Bm = (z == 0) ? g_wq : (z == 1) ? g_wk : g_wv;
    const float* bias = (z == 0) ? bq : (z == 1) ? bk : bv;
    float* C = (z == 0) ? g_q : (z == 1) ? g_k : g_v;
    gemm_core(A, Bm, bias, C, cH, cH, cH, cH,
              blockIdx.y * 128, blockIdx.x * 128, z < 2);
}

// generic batched GEMM (z = batch)
__global__ __launch_bounds__(256, 2)
void gemm_bat(const float* __restrict__ A, const float* __restrict__ Bm,
              const float* __restrict__ bias, float* __restrict__ C,
              int Kd, int lda, int ldb, int ldc,
              size_t strA, size_t strB, size_t strC, int round_out) {
    gemm_core(A + blockIdx.z * strA, Bm + blockIdx.z * strB, bias,
              C + blockIdx.z * strC, Kd, lda, ldb, ldc,
              blockIdx.y * 128, blockIdx.x * 128, round_out != 0);
}

// ---------------- softmax ---------------------------------------------------
__global__ void softmax_kernel(float* __restrict__ Sc, float scale) {
    const size_t row = blockIdx.x;
    float* p = Sc + row * (size_t)cS;
    const int tid = threadIdx.x;
    __shared__ float smax[8];
    __shared__ float ssum[8];

    float v[8];
    float m = -CUDART_INF_F;
#pragma unroll
    for (int i = 0; i < 8; i++) {
        v[i] = p[tid + i * 256] * scale;
        m = fmaxf(m, v[i]);
    }
#pragma unroll
    for (int o = 16; o > 0; o >>= 1)
        m = fmaxf(m, __shfl_xor_sync(0xffffffffu, m, o));
    if ((tid & 31) == 0) smax[tid >> 5] = m;
    __syncthreads();
    m = smax[0];
#pragma unroll
    for (int w = 1; w < 8; w++) m = fmaxf(m, smax[w]);

    float s = 0.f;
#pragma unroll
    for (int i = 0; i < 8; i++) {
        v[i] = expf(v[i] - m);
        s += v[i];
    }
#pragma unroll
    for (int o = 16; o > 0; o >>= 1)
        s += __shfl_xor_sync(0xffffffffu, s, o);
    if ((tid & 31) == 0) ssum[tid >> 5] = s;
    __syncthreads();
    s = 0.f;
#pragma unroll
    for (int w = 0; w < 8; w++) s += ssum[w];
    const float inv = 1.0f / s;
#pragma unroll
    for (int i = 0; i < 8; i++) p[tid + i * 256] = tf32r(v[i] * inv);
}

// ---------------- launch ----------------------------------------------------
extern "C" void kernel_launch(void* const* d_in, const int* in_sizes, int n_in,
                              void* d_out, int out_size) {
    const float* query = (const float*)d_in[0];
    const float* key_  = (const float*)d_in[1];
    const float* value = (const float*)d_in[2];
    const float* Wq = (const float*)d_in[3];
    const float* bq = (const float*)d_in[4];
    const float* Wk = (const float*)d_in[5];
    const float* bk = (const float*)d_in[6];
    const float* Wv = (const float*)d_in[7];
    const float* bv = (const float*)d_in[8];
    const float* Wo = (const float*)d_in[9];
    const float* bo = (const float*)d_in[10];
    float* out = (float*)d_out;

    float *p_v, *p_vT, *p_s, *p_ctx, *p_q, *p_k, *p_wo;
    cudaGetSymbolAddress((void**)&p_v, g_v);
    cudaGetSymbolAddress((void**)&p_vT, g_vT);
    cudaGetSymbolAddress((void**)&p_s, g_s);
    cudaGetSymbolAddress((void**)&p_ctx, g_ctx);
    cudaGetSymbolAddress((void**)&p_q, g_q);
    cudaGetSymbolAddress((void**)&p_k, g_k);
    cudaGetSymbolAddress((void**)&p_wo, g_wo);

    cudaFuncSetAttribute(gemm3_proj,
                         cudaFuncAttributeMaxDynamicSharedMemorySize, GEMM_SMEM);
    cudaFuncSetAttribute(gemm_bat,
                         cudaFuncAttributeMaxDynamicSharedMemorySize, GEMM_SMEM);

    // 1) RoPE tables; RoPE(q,k) + round(v)
    rope_tables_kernel<<<(cS * cH2 + 255) / 256, 256>>>();
    rope_apply_v_kernel<<<(int)(MHz / 256), 256>>>(query, key_, value);

    // 2) round all weights (one launch)
    round_weights_kernel<<<dim3((unsigned)(WN / 4 / 256), 4), 256>>>(Wq, Wk, Wv, Wo);

    // 3) fused q/k/v projections (grid.z = 3)
    gemm3_proj<<<dim3(16, 64, 3), 256, GEMM_SMEM>>>(bq, bk, bv);

    // 4) transpose v -> vT [H][M]
    transpose_round_kernel<<<dim3(cH / 32, cM / 32), dim3(32, 8)>>>(p_v, p_vT);

    // 5) scores = q @ k^T (batched over B)
    gemm_bat<<<dim3(16, 16, cB), 256, GEMM_SMEM>>>(p_q, p_k, nullptr, p_s,
                                                   cH, cH, cH, cS, SH, SH, SSz, 0);

    // 6) softmax
    const float scale = 1.0f / sqrtf((float)cH);
    softmax_kernel<<<cB * cS, 256>>>(p_s, scale);

    // 7) context = probs @ vT^T (batched)
    gemm_bat<<<dim3(16, 16, cB), 256, GEMM_SMEM>>>(p_s, p_vT, nullptr, p_ctx,
                                                   cS, cS, cM, cH, SSz, (size_t)cS, SH, 1);

    // 8) out = ctx @ Wo^T + bo
    gemm_bat<<<dim3(16, 64, 1), 256, GEMM_SMEM>>>(p_ctx, p_wo, bo, out,
                                                  cH, cH, cH, cH, 0, 0, 0, 0);
}

// round 11
// speedup vs baseline: 4.3715x; 1.0078x over previous
#include <cuda_runtime.h>
#include <math.h>
#include <math_constants.h>
#include <stdint.h>

// Problem constants
constexpr int cB = 4;
constexpr int cS = 2048;
constexpr int cH = 2048;
constexpr int cH2 = cH / 2;
constexpr int cM = cB * cS;               // 8192
constexpr size_t SH = (size_t)cS * cH;
constexpr size_t SSz = (size_t)cS * cS;
constexpr size_t MHz = (size_t)cM * cH;
constexpr size_t WN = (size_t)cH * cH;

// ---------------- scratch ---------------------------------------------------
__device__ float g_cos[SH / 2];   // only first half (mirrored)
__device__ float g_sin[SH / 2];
__device__ float g_qrot[MHz];
__device__ float g_krot[MHz];
__device__ float g_vin[MHz];
__device__ float g_wq[WN];
__device__ float g_wk[WN];
__device__ float g_wv[WN];
__device__ float g_wo[WN];
__device__ float g_q[MHz];
__device__ float g_k[MHz];
__device__ float g_v[MHz];
__device__ float g_vT[MHz];
__device__ float g_s[(size_t)cB * SSz];
__device__ float g_ctx[MHz];

// ---------------- helpers ---------------------------------------------------
__device__ __forceinline__ float tf32r(float x) {
    uint32_t u;
    asm("cvt.rna.tf32.f32 %0, %1;" : "=r"(u) : "f"(x));
    return __uint_as_float(u);
}

#define CPA16(smem_u32, gptr) \
    asm volatile("cp.async.cg.shared.global [%0], [%1], 16;" :: "r"(smem_u32), "l"(gptr))

#define LDSM4(r0, r1, r2, r3, a) \
    asm volatile("ldmatrix.sync.aligned.m8n8.x4.shared.b16 {%0,%1,%2,%3}, [%4];" \
                 : "=r"(r0), "=r"(r1), "=r"(r2), "=r"(r3) : "r"(a))

#define LDSM2(r0, r1, a) \
    asm volatile("ldmatrix.sync.aligned.m8n8.x2.shared.b16 {%0,%1}, [%2];" \
                 : "=r"(r0), "=r"(r1) : "r"(a))

// ---------------- RoPE tables (first half only; second half mirrors) --------
__global__ void rope_tables_kernel() {
    int idx = blockIdx.x * blockDim.x + threadIdx.x;
    if (idx >= cS * cH2) return;
    int s = idx / cH2;
    int j = idx % cH2;
    float f = (float)pow(10000.0, -2.0 * (double)j / (double)cH);
    float ang = (float)s * f;
    float sn, cs;
    sincosf(ang, &sn, &cs);
    g_cos[(size_t)s * cH2 + j] = cs;
    g_sin[(size_t)s * cH2 + j] = sn;
}

// RoPE on q,k + tf32-round v; each thread handles a (h, h+H/2) float4 PAIR.
// out1 = q1*c - q2*s ; out2 = q2*c + q1*s  (identical expressions to before)
__global__ void rope_apply_v_kernel(const float* __restrict__ q,
                                    const float* __restrict__ k,
                                    const float* __restrict__ v) {
    constexpr int J4 = cH2 / 4;               // 256 float4 per half-row
    size_t idx = (size_t)blockIdx.x * blockDim.x + threadIdx.x;
    if (idx >= (size_t)cM * J4) return;
    const int m = (int)(idx / J4);
    const int j4 = (int)(idx % J4);
    const int s = m & (cS - 1);
    const size_t tbl = (size_t)s * cH2 + j4 * 4;
    const size_t b1 = (size_t)m * cH + j4 * 4;
    const size_t b2 = b1 + cH2;

    float4 c  = *(const float4*)(g_cos + tbl);
    float4 sn = *(const float4*)(g_sin + tbl);

    float4 q1 = *(const float4*)(q + b1);
    float4 q2 = *(const float4*)(q + b2);
    float4 o1, o2;
    o1.x = tf32r(q1.x * c.x - q2.x * sn.x); o2.x = tf32r(q2.x * c.x + q1.x * sn.x);
    o1.y = tf32r(q1.y * c.y - q2.y * sn.y); o2.y = tf32r(q2.y * c.y + q1.y * sn.y);
    o1.z = tf32r(q1.z * c.z - q2.z * sn.z); o2.z = tf32r(q2.z * c.z + q1.z * sn.z);
    o1.w = tf32r(q1.w * c.w - q2.w * sn.w); o2.w = tf32r(q2.w * c.w + q1.w * sn.w);
    *(float4*)(g_qrot + b1) = o1;
    *(float4*)(g_qrot + b2) = o2;

    float4 k1 = *(const float4*)(k + b1);
    float4 k2 = *(const float4*)(k + b2);
    o1.x = tf32r(k1.x * c.x - k2.x * sn.x); o2.x = tf32r(k2.x * c.x + k1.x * sn.x);
    o1.y = tf32r(k1.y * c.y - k2.y * sn.y); o2.y = tf32r(k2.y * c.y + k1.y * sn.y);
    o1.z = tf32r(k1.z * c.z - k2.z * sn.z); o2.z = tf32r(k2.z * c.z + k1.z * sn.z);
    o1.w = tf32r(k1.w * c.w - k2.w * sn.w); o2.w = tf32r(k2.w * c.w + k1.w * sn.w);
    *(float4*)(g_krot + b1) = o1;
    *(float4*)(g_krot + b2) = o2;

    float4 v1 = *(const float4*)(v + b1);
    float4 v2 = *(const float4*)(v + b2);
    v1.x = tf32r(v1.x); v1.y = tf32r(v1.y); v1.z = tf32r(v1.z); v1.w = tf32r(v1.w);
    v2.x = tf32r(v2.x); v2.y = tf32r(v2.y); v2.z = tf32r(v2.z); v2.w = tf32r(v2.w);
    *(float4*)(g_vin + b1) = v1;
    *(float4*)(g_vin + b2) = v2;
}

// round all 4 weight matrices: grid (WN/4/256, 4)
__global__ void round_weights_kernel(const float* __restrict__ w0,
                                     const float* __restrict__ w1,
                                     const float* __restrict__ w2,
                                     const float* __restrict__ w3) {
    const float* src = (blockIdx.y == 0) ? w0 : (blockIdx.y == 1) ? w1
                     : (blockIdx.y == 2) ? w2 : w3;
    float* dst = (blockIdx.y == 0) ? g_wq : (blockIdx.y == 1) ? g_wk
               : (blockIdx.y == 2) ? g_wv : g_wo;
    size_t i = (size_t)blockIdx.x * blockDim.x + threadIdx.x;
    float4 v = ((const float4*)src)[i];
    v.x = tf32r(v.x); v.y = tf32r(v.y); v.z = tf32r(v.z); v.w = tf32r(v.w);
    ((float4*)dst)[i] = v;
}

__global__ void transpose_round_kernel(const float* __restrict__ in,
                                       float* __restrict__ out) {
    __shared__ float t[32][33];
    int x = blockIdx.x * 32 + threadIdx.x;
    int y0 = blockIdx.y * 32 + threadIdx.y;
#pragma unroll
    for (int j = 0; j < 32; j += 8)
        t[threadIdx.y + j][threadIdx.x] = in[(size_t)(y0 + j) * cH + x];
    __syncthreads();
    int ox = blockIdx.y * 32 + threadIdx.x;
    int oy = blockIdx.x * 32 + threadIdx.y;
#pragma unroll
    for (int j = 0; j < 32; j += 8)
        out[(size_t)(oy + j) * cM + ox] = tf32r(t[threadIdx.x][threadIdx.y + j]);
}

// ---------------- mma.sync TF32 GEMM core -----------------------------------
constexpr int BK = 32;
constexpr int TILE_B = 128 * BK * 4;
constexpr int STG = 2 * TILE_B;
constexpr int NSTG = 3;
constexpr int GEMM_SMEM = NSTG * STG + 1024;  // 99328 (2 CTA/SM)

__device__ __forceinline__ void gemm_core(
    const float* __restrict__ Ab, const float* __restrict__ Bb,
    const float* __restrict__ bias, float* __restrict__ Cb,
    int Kd, int lda, int ldb, int ldc, int bm, int bn, bool round_out) {
    extern __shared__ float smf[];
    uint32_t sbase = (uint32_t)__cvta_generic_to_shared(smf);
    sbase = (sbase + 1023u) & ~1023u;

    const int tid = threadIdx.x;
    const int lane = tid & 31;
    const int w = tid >> 5;
    const int wm = (w >> 2) * 64;
    const int wn = (w & 3) * 32;
    const int g = lane >> 2;
    const int tig = lane & 3;
    const int nk = Kd / BK;

    const int r0 = tid >> 3;
    const int ch = tid & 7;
    const uint32_t swoff = (uint32_t)((ch * 16) ^ ((r0 & 7) << 4));
    const uint32_t ldOffA = (uint32_t)(r0 * 128) + swoff;
    const float* gA0 = Ab + (size_t)(bm + r0) * lda + ch * 4;
    const float* gB0 = Bb + (size_t)(bn + r0) * ldb + ch * 4;
    const size_t gAs = 32 * (size_t)lda;
    const size_t gBs = 32 * (size_t)ldb;

    const int aRowOff = ((lane >> 3) & 1) * 8 + (lane & 7);
    const uint32_t aCS = (uint32_t)((lane >> 4) * 16);
    uint32_t aRB[4], aRX[4];
#pragma unroll
    for (int i = 0; i < 4; i++) {
        int row = wm + i * 16 + aRowOff;
        aRB[i] = (uint32_t)(row * 128);
        aRX[i] = (uint32_t)((row & 7) << 4);
    }
    const int bRowOff = lane & 7;
    const uint32_t bCS = (uint32_t)(((lane >> 3) & 1) * 16);
    uint32_t bRB[4], bRX[4];
#pragma unroll
    for (int j = 0; j < 4; j++) {
        int row = wn + j * 8 + bRowOff;
        bRB[j] = (uint32_t)(row * 128);
        bRX[j] = (uint32_t)((row & 7) << 4);
    }

    float acc[4][4][4];
#pragma unroll
    for (int i = 0; i < 4; i++)
#pragma unroll
        for (int j = 0; j < 4; j++)
#pragma unroll
            for (int r = 0; r < 4; r++) acc[i][j][r] = 0.f;

#pragma unroll
    for (int t = 0; t < 2; t++) {
        const uint32_t ds = sbase + t * STG;
        const float* ga = gA0 + (size_t)t * BK;
        const float* gb = gB0 + (size_t)t * BK;
#pragma unroll
        for (int u = 0; u < 4; u++) {
            CPA16(ds + ldOffA + u * 4096, ga + u * gAs);
            CPA16(ds + TILE_B + ldOffA + u * 4096, gb + u * gBs);
        }
        asm volatile("cp.async.commit_group;");
    }

    int s = 0, sp = 2;
    for (int t = 0; t < nk; t++) {
        asm volatile("cp.async.wait_group 1;");
        __syncthreads();

        const uint32_t aB = sbase + s * STG;
        const uint32_t bB = aB + TILE_B;

        // ---- ks=0 fragment loads FIRST (start tensor work early) ----
        uint32_t af[4][4], bf[4][2];
#pragma unroll
        for (int i = 0; i < 4; i++)
            LDSM4(af[i][0], af[i][1], af[i][2], af[i][3],
                  aB + aRB[i] + (aCS ^ aRX[i]));
#pragma unroll
        for (int j = 0; j < 4; j++)
            LDSM2(bf[j][0], bf[j][1], bB + bRB[j] + (bCS ^ bRX[j]));

        // ---- prefetch next tile (overlaps with ks=0 MMAs) ----
        if (t + 2 < nk) {
            const uint32_t ds = sbase + sp * STG;
            const float* ga = gA0 + (size_t)(t + 2) * BK;
            const float* gb = gB0 + (size_t)(t + 2) * BK;
#pragma unroll
            for (int u = 0; u < 4; u++) {
                CPA16(ds + ldOffA + u * 4096, ga + u * gAs);
                CPA16(ds + TILE_B + ldOffA + u * 4096, gb + u * gBs);
            }
        }
        asm volatile("cp.async.commit_group;");

#pragma unroll
        for (int i = 0; i < 4; i++)
#pragma unroll
            for (int j = 0; j < 4; j++) {
                asm volatile(
                    "mma.sync.aligned.m16n8k8.row.col.f32.tf32.tf32.f32 "
                    "{%0,%1,%2,%3}, {%4,%5,%6,%7}, {%8,%9}, {%0,%1,%2,%3};"
                    : "+f"(acc[i][j][0]), "+f"(acc[i][j][1]),
                      "+f"(acc[i][j][2]), "+f"(acc[i][j][3])
                    : "r"(af[i][0]), "r"(af[i][1]), "r"(af[i][2]), "r"(af[i][3]),
                      "r"(bf[j][0]), "r"(bf[j][1]));
            }

#pragma unroll
        for (int ks = 1; ks < 4; ks++) {
            const uint32_t kcol = (uint32_t)(ks * 32);
#pragma unroll
            for (int i = 0; i < 4; i++)
                LDSM4(af[i][0], af[i][1], af[i][2], af[i][3],
                      aB + aRB[i] + ((kcol + aCS) ^ aRX[i]));
#pragma unroll
            for (int j = 0; j < 4; j++)
                LDSM2(bf[j][0], bf[j][1],
                      bB + bRB[j] + ((kcol + bCS) ^ bRX[j]));
#pragma unroll
            for (int i = 0; i < 4; i++)
#pragma unroll
                for (int j = 0; j < 4; j++) {
                    asm volatile(
                        "mma.sync.aligned.m16n8k8.row.col.f32.tf32.tf32.f32 "
                        "{%0,%1,%2,%3}, {%4,%5,%6,%7}, {%8,%9}, {%0,%1,%2,%3};"
                        : "+f"(acc[i][j][0]), "+f"(acc[i][j][1]),
                          "+f"(acc[i][j][2]), "+f"(acc[i][j][3])
                        : "r"(af[i][0]), "r"(af[i][1]), "r"(af[i][2]), "r"(af[i][3]),
                          "r"(bf[j][0]), "r"(bf[j][1]));
                }
        }
        s = (s == NSTG - 1) ? 0 : s + 1;
        sp = (sp == NSTG - 1) ? 0 : sp + 1;
    }

#pragma unroll
    for (int i = 0; i < 4; i++) {
        const int rr0 = bm + wm + i * 16 + g;
        const int rr1 = rr0 + 8;
#pragma unroll
        for (int j = 0; j < 4; j++) {
            const int cc = bn + wn + j * 8 + 2 * tig;
            float b0 = 0.f, b1 = 0.f;
            if (bias) { b0 = bias[cc]; b1 = bias[cc + 1]; }
            float2 v0, v1;
            v0.x = acc[i][j][0] + b0; v0.y = acc[i][j][1] + b1;
            v1.x = acc[i][j][2] + b0; v1.y = acc[i][j][3] + b1;
            if (round_out) {
                v0.x = tf32r(v0.x); v0.y = tf32r(v0.y);
                v1.x = tf32r(v1.x); v1.y = tf32r(v1.y);
            }
            *(float2*)(Cb + (size_t)rr0 * ldc + cc) = v0;
            *(float2*)(Cb + (size_t)rr1 * ldc + cc) = v1;
        }
    }
}

__global__ __launch_bounds__(256, 2)
void gemm3_proj(const float* __restrict__ bq, const float* __restrict__ bk,
                const float* __restrict__ bv) {
    const int z = blockIdx.z;
    const float* A = (z == 0) ? g_qrot : (z == 1) ? g_krot : g_vin;
    const float* Bm = (z == 0) ? g_wq : (z == 1) ? g_wk : g_wv;
    const float* bias = (z == 0) ? bq : (z == 1) ? bk : bv;
    float* C = (z == 0) ? g_q : (z == 1) ? g_k : g_v;
    gemm_core(A, Bm, bias, C, cH, cH, cH, cH,
              blockIdx.y * 128, blockIdx.x * 128, z < 2);
}

__global__ __launch_bounds__(256, 2)
void gemm_bat(const float* __restrict__ A, const float* __restrict__ Bm,
              const float* __restrict__ bias, float* __restrict__ C,
              int Kd, int lda, int ldb, int ldc,
              size_t strA, size_t strB, size_t strC, int round_out) {
    gemm_core(A + blockIdx.z * strA, Bm + blockIdx.z * strB, bias,
              C + blockIdx.z * strC, Kd, lda, ldb, ldc,
              blockIdx.y * 128, blockIdx.x * 128, round_out != 0);
}

// ---------------- softmax ---------------------------------------------------
__global__ void softmax_kernel(float* __restrict__ Sc, float scale) {
    const size_t row = blockIdx.x;
    float* p = Sc + row * (size_t)cS;
    const int tid = threadIdx.x;
    __shared__ float smax[8];
    __shared__ float ssum[8];

    float v[8];
    float m = -CUDART_INF_F;
#pragma unroll
    for (int i = 0; i < 8; i++) {
        v[i] = p[tid + i * 256] * scale;
        m = fmaxf(m, v[i]);
    }
#pragma unroll
    for (int o = 16; o > 0; o >>= 1)
        m = fmaxf(m, __shfl_xor_sync(0xffffffffu, m, o));
    if ((tid & 31) == 0) smax[tid >> 5] = m;
    __syncthreads();
    m = smax[0];
#pragma unroll
    for (int w = 1; w < 8; w++) m = fmaxf(m, smax[w]);

    float s = 0.f;
#pragma unroll
    for (int i = 0; i < 8; i++) {
        v[i] = expf(v[i] - m);
        s += v[i];
    }
#pragma unroll
    for (int o = 16; o > 0; o >>= 1)
        s += __shfl_xor_sync(0xffffffffu, s, o);
    if ((tid & 31) == 0) ssum[tid >> 5] = s;
    __syncthreads();
    s = 0.f;
#pragma unroll
    for (int w = 0; w < 8; w++) s += ssum[w];
    const float inv = 1.0f / s;
#pragma unroll
    for (int i = 0; i < 8; i++) p[tid + i * 256] = tf32r(v[i] * inv);
}

// ---------------- launch ----------------------------------------------------
extern "C" void kernel_launch(void* const* d_in, const int* in_sizes, int n_in,
                              void* d_out, int out_size) {
    const float* query = (const float*)d_in[0];
    const float* key_  = (const float*)d_in[1];
    const float* value = (const float*)d_in[2];
    const float* Wq = (const float*)d_in[3];
    const float* bq = (const float*)d_in[4];
    const float* Wk = (const float*)d_in[5];
    const float* bk = (const float*)d_in[6];
    const float* Wv = (const float*)d_in[7];
    const float* bv = (const float*)d_in[8];
    const float* Wo = (const float*)d_in[9];
    const float* bo = (const float*)d_in[10];
    float* out = (float*)d_out;

    float *p_v, *p_vT, *p_s, *p_ctx, *p_q, *p_k, *p_wo;
    cudaGetSymbolAddress((void**)&p_v, g_v);
    cudaGetSymbolAddress((void**)&p_vT, g_vT);
    cudaGetSymbolAddress((void**)&p_s, g_s);
    cudaGetSymbolAddress((void**)&p_ctx, g_ctx);
    cudaGetSymbolAddress((void**)&p_q, g_q);
    cudaGetSymbolAddress((void**)&p_k, g_k);
    cudaGetSymbolAddress((void**)&p_wo, g_wo);

    cudaFuncSetAttribute(gemm3_proj,
                         cudaFuncAttributeMaxDynamicSharedMemorySize, GEMM_SMEM);
    cudaFuncSetAttribute(gemm_bat,
                         cudaFuncAttributeMaxDynamicSharedMemorySize, GEMM_SMEM);

    // 1) RoPE tables; RoPE(q,k) + round(v) pair-processed
    rope_tables_kernel<<<(cS * cH2 + 255) / 256, 256>>>();
    rope_apply_v_kernel<<<(int)((size_t)cM * (cH2 / 4) / 256), 256>>>(query, key_, value);

    // 2) round all weights (one launch)
    round_weights_kernel<<<dim3((unsigned)(WN / 4 / 256), 4), 256>>>(Wq, Wk, Wv, Wo);

    // 3) fused q/k/v projections
    gemm3_proj<<<dim3(16, 64, 3), 256, GEMM_SMEM>>>(bq, bk, bv);

    // 4) transpose v -> vT [H][M]
    transpose_round_kernel<<<dim3(cH / 32, cM / 32), dim3(32, 8)>>>(p_v, p_vT);

    // 5) scores = q @ k^T (batched over B)
    gemm_bat<<<dim3(16, 16, cB), 256, GEMM_SMEM>>>(p_q, p_k, nullptr, p_s,
                                                   cH, cH, cH, cS, SH, SH, SSz, 0);

    // 6) softmax
    const float scale = 1.0f / sqrtf((float)cH);
    softmax_kernel<<<cB * cS, 256>>>(p_s, scale);

    // 7) context = probs @ vT^T (batched)
    gemm_bat<<<dim3(16, 16, cB), 256, GEMM_SMEM>>>(p_s, p_vT, nullptr, p_ctx,
                                                   cS, cS, cM, cH, SSz, (size_t)cS, SH, 1);

    // 8) out = ctx @ Wo^T + bo
    gemm_bat<<<dim3(16, 64, 1), 256, GEMM_SMEM>>>(p_ctx, p_wo, bo, out,
                                                  cH, cH, cH, cH, 0, 0, 0, 0);
}

// round 12
// speedup vs baseline: 4.5365x; 1.0378x over previous
#include <cuda_runtime.h>
#include <math.h>
#include <math_constants.h>
#include <stdint.h>

// Problem constants
constexpr int cB = 4;
constexpr int cS = 2048;
constexpr int cH = 2048;
constexpr int cH2 = cH / 2;
constexpr int cM = cB * cS;               // 8192
constexpr size_t SH = (size_t)cS * cH;
constexpr size_t SSz = (size_t)cS * cS;
constexpr size_t MHz = (size_t)cM * cH;
constexpr size_t WN = (size_t)cH * cH;

// ---------------- scratch ---------------------------------------------------
__device__ float g_cos[SH / 2];   // only first half (mirrored)
__device__ float g_sin[SH / 2];
__device__ float g_qrot[MHz];
__device__ float g_krot[MHz];
__device__ float g_vin[MHz];
__device__ float g_wq[WN];
__device__ float g_wk[WN];
__device__ float g_wv[WN];
__device__ float g_wo[WN];
__device__ float g_q[MHz];
__device__ float g_k[MHz];
__device__ float g_vT[MHz];       // v projected AND transposed [H][M]
__device__ float g_s[(size_t)cB * SSz];
__device__ float g_ctx[MHz];

// ---------------- helpers ---------------------------------------------------
__device__ __forceinline__ float tf32r(float x) {
    uint32_t u;
    asm("cvt.rna.tf32.f32 %0, %1;" : "=r"(u) : "f"(x));
    return __uint_as_float(u);
}

#define CPA16(smem_u32, gptr) \
    asm volatile("cp.async.cg.shared.global [%0], [%1], 16;" :: "r"(smem_u32), "l"(gptr))

#define LDSM4(r0, r1, r2, r3, a) \
    asm volatile("ldmatrix.sync.aligned.m8n8.x4.shared.b16 {%0,%1,%2,%3}, [%4];" \
                 : "=r"(r0), "=r"(r1), "=r"(r2), "=r"(r3) : "r"(a))

// ---------------- RoPE tables (first half only; second half mirrors) --------
__global__ void rope_tables_kernel() {
    int idx = blockIdx.x * blockDim.x + threadIdx.x;
    if (idx >= cS * cH2) return;
    int s = idx / cH2;
    int j = idx % cH2;
    float f = (float)pow(10000.0, -2.0 * (double)j / (double)cH);
    float ang = (float)s * f;
    float sn, cs;
    sincosf(ang, &sn, &cs);
    g_cos[(size_t)s * cH2 + j] = cs;
    g_sin[(size_t)s * cH2 + j] = sn;
}

// RoPE on q,k + tf32-round v; each thread handles a (h, h+H/2) float4 PAIR.
__global__ void rope_apply_v_kernel(const float* __restrict__ q,
                                    const float* __restrict__ k,
                                    const float* __restrict__ v) {
    constexpr int J4 = cH2 / 4;               // 256 float4 per half-row
    size_t idx = (size_t)blockIdx.x * blockDim.x + threadIdx.x;
    if (idx >= (size_t)cM * J4) return;
    const int m = (int)(idx / J4);
    const int j4 = (int)(idx % J4);
    const int s = m & (cS - 1);
    const size_t tbl = (size_t)s * cH2 + j4 * 4;
    const size_t b1 = (size_t)m * cH + j4 * 4;
    const size_t b2 = b1 + cH2;

    float4 c  = *(const float4*)(g_cos + tbl);
    float4 sn = *(const float4*)(g_sin + tbl);

    float4 q1 = *(const float4*)(q + b1);
    float4 q2 = *(const float4*)(q + b2);
    float4 o1, o2;
    o1.x = tf32r(q1.x * c.x - q2.x * sn.x); o2.x = tf32r(q2.x * c.x + q1.x * sn.x);
    o1.y = tf32r(q1.y * c.y - q2.y * sn.y); o2.y = tf32r(q2.y * c.y + q1.y * sn.y);
    o1.z = tf32r(q1.z * c.z - q2.z * sn.z); o2.z = tf32r(q2.z * c.z + q1.z * sn.z);
    o1.w = tf32r(q1.w * c.w - q2.w * sn.w); o2.w = tf32r(q2.w * c.w + q1.w * sn.w);
    *(float4*)(g_qrot + b1) = o1;
    *(float4*)(g_qrot + b2) = o2;

    float4 k1 = *(const float4*)(k + b1);
    float4 k2 = *(const float4*)(k + b2);
    o1.x = tf32r(k1.x * c.x - k2.x * sn.x); o2.x = tf32r(k2.x * c.x + k1.x * sn.x);
    o1.y = tf32r(k1.y * c.y - k2.y * sn.y); o2.y = tf32r(k2.y * c.y + k1.y * sn.y);
    o1.z = tf32r(k1.z * c.z - k2.z * sn.z); o2.z = tf32r(k2.z * c.z + k1.z * sn.z);
    o1.w = tf32r(k1.w * c.w - k2.w * sn.w); o2.w = tf32r(k2.w * c.w + k1.w * sn.w);
    *(float4*)(g_krot + b1) = o1;
    *(float4*)(g_krot + b2) = o2;

    float4 v1 = *(const float4*)(v + b1);
    float4 v2 = *(const float4*)(v + b2);
    v1.x = tf32r(v1.x); v1.y = tf32r(v1.y); v1.z = tf32r(v1.z); v1.w = tf32r(v1.w);
    v2.x = tf32r(v2.x); v2.y = tf32r(v2.y); v2.z = tf32r(v2.z); v2.w = tf32r(v2.w);
    *(float4*)(g_vin + b1) = v1;
    *(float4*)(g_vin + b2) = v2;
}

// round all 4 weight matrices: grid (WN/4/256, 4)
__global__ void round_weights_kernel(const float* __restrict__ w0,
                                     const float* __restrict__ w1,
                                     const float* __restrict__ w2,
                                     const float* __restrict__ w3) {
    const float* src = (blockIdx.y == 0) ? w0 : (blockIdx.y == 1) ? w1
                     : (blockIdx.y == 2) ? w2 : w3;
    float* dst = (blockIdx.y == 0) ? g_wq : (blockIdx.y == 1) ? g_wk
               : (blockIdx.y == 2) ? g_wv : g_wo;
    size_t i = (size_t)blockIdx.x * blockDim.x + threadIdx.x;
    float4 v = ((const float4*)src)[i];
    v.x = tf32r(v.x); v.y = tf32r(v.y); v.z = tf32r(v.z); v.w = tf32r(v.w);
    ((float4*)dst)[i] = v;
}

// ---------------- mma.sync TF32 GEMM core -----------------------------------
// C[m,n] = sum_k A[m,k] * B[n,k] (+bias[n]); B [N][K] K-major.
// Block 128x128x32, 256 threads, 3-stage cp.async, ldmatrix frags, occ 2.
// MODE: 0 = plain store, 1 = tf32-rounded store, 2 = TRANSPOSED store into
//       [N][M] layout (ld = cM) with tf32 rounding — used for the V proj.
constexpr int BK = 32;
constexpr int TILE_B = 128 * BK * 4;
constexpr int STG = 2 * TILE_B;
constexpr int NSTG = 3;
constexpr int GEMM_SMEM = NSTG * STG + 1024;  // 99328 (2 CTA/SM)

template<int MODE>
__device__ __forceinline__ void gemm_core(
    const float* __restrict__ Ab, const float* __restrict__ Bb,
    const float* __restrict__ bias, float* __restrict__ Cb,
    int Kd, int lda, int ldb, int ldc, int bm, int bn) {
    extern __shared__ float smf[];
    uint32_t sbase = (uint32_t)__cvta_generic_to_shared(smf);
    sbase = (sbase + 1023u) & ~1023u;

    const int tid = threadIdx.x;
    const int lane = tid & 31;
    const int w = tid >> 5;
    const int wm = (w >> 2) * 64;
    const int wn = (w & 3) * 32;
    const int g = lane >> 2;
    const int tig = lane & 3;
    const int nk = Kd / BK;

    const int r0 = tid >> 3;
    const int ch = tid & 7;
    const uint32_t swoff = (uint32_t)((ch * 16) ^ ((r0 & 7) << 4));
    const uint32_t ldOffA = (uint32_t)(r0 * 128) + swoff;
    const float* gA0 = Ab + (size_t)(bm + r0) * lda + ch * 4;
    const float* gB0 = Bb + (size_t)(bn + r0) * ldb + ch * 4;
    const size_t gAs = 32 * (size_t)lda;
    const size_t gBs = 32 * (size_t)ldb;

    // A fragment addresses (ldmatrix x4: rows g/g+8 x k lo/hi)
    const int aRowOff = ((lane >> 3) & 1) * 8 + (lane & 7);
    const uint32_t aCS = (uint32_t)((lane >> 4) * 16);
    uint32_t aRB[4], aRX[4];
#pragma unroll
    for (int i = 0; i < 4; i++) {
        int row = wm + i * 16 + aRowOff;
        aRB[i] = (uint32_t)(row * 128);
        aRX[i] = (uint32_t)((row & 7) << 4);
    }
    // B fragment addresses (ldmatrix x4 covers j-pair: rows j*8..j*8+15, k lo/hi)
    const uint32_t bCS = (uint32_t)(((lane >> 3) & 1) * 16);
    uint32_t bRB[2], bRX[2];
#pragma unroll
    for (int p = 0; p < 2; p++) {
        int row = wn + p * 16 + ((lane >> 4) * 8) + (lane & 7);
        bRB[p] = (uint32_t)(row * 128);
        bRX[p] = (uint32_t)((row & 7) << 4);
    }

    float acc[4][4][4];
#pragma unroll
    for (int i = 0; i < 4; i++)
#pragma unroll
        for (int j = 0; j < 4; j++)
#pragma unroll
            for (int r = 0; r < 4; r++) acc[i][j][r] = 0.f;

#pragma unroll
    for (int t = 0; t < 2; t++) {
        const uint32_t ds = sbase + t * STG;
        const float* ga = gA0 + (size_t)t * BK;
        const float* gb = gB0 + (size_t)t * BK;
#pragma unroll
        for (int u = 0; u < 4; u++) {
            CPA16(ds + ldOffA + u * 4096, ga + u * gAs);
            CPA16(ds + TILE_B + ldOffA + u * 4096, gb + u * gBs);
        }
        asm volatile("cp.async.commit_group;");
    }

    int s = 0, sp = 2;
    for (int t = 0; t < nk; t++) {
        asm volatile("cp.async.wait_group 1;");
        __syncthreads();

        if (t + 2 < nk) {
            const uint32_t ds = sbase + sp * STG;
            const float* ga = gA0 + (size_t)(t + 2) * BK;
            const float* gb = gB0 + (size_t)(t + 2) * BK;
#pragma unroll
            for (int u = 0; u < 4; u++) {
                CPA16(ds + ldOffA + u * 4096, ga + u * gAs);
                CPA16(ds + TILE_B + ldOffA + u * 4096, gb + u * gBs);
            }
        }
        asm volatile("cp.async.commit_group;");

        const uint32_t aB = sbase + s * STG;
        const uint32_t bB = aB + TILE_B;
#pragma unroll
        for (int ks = 0; ks < 4; ks++) {
            const uint32_t kcol = (uint32_t)(ks * 32);
            uint32_t af[4][4], bf[4][2];
#pragma unroll
            for (int i = 0; i < 4; i++)
                LDSM4(af[i][0], af[i][1], af[i][2], af[i][3],
                      aB + aRB[i] + ((kcol + aCS) ^ aRX[i]));
#pragma unroll
            for (int p = 0; p < 2; p++)
                LDSM4(bf[2 * p][0], bf[2 * p][1], bf[2 * p + 1][0], bf[2 * p + 1][1],
                      bB + bRB[p] + ((kcol + bCS) ^ bRX[p]));
#pragma unroll
            for (int i = 0; i < 4; i++)
#pragma unroll
                for (int j = 0; j < 4; j++) {
                    asm volatile(
                        "mma.sync.aligned.m16n8k8.row.col.f32.tf32.tf32.f32 "
                        "{%0,%1,%2,%3}, {%4,%5,%6,%7}, {%8,%9}, {%0,%1,%2,%3};"
                        : "+f"(acc[i][j][0]), "+f"(acc[i][j][1]),
                          "+f"(acc[i][j][2]), "+f"(acc[i][j][3])
                        : "r"(af[i][0]), "r"(af[i][1]), "r"(af[i][2]), "r"(af[i][3]),
                          "r"(bf[j][0]), "r"(bf[j][1]));
                }
        }
        s = (s == NSTG - 1) ? 0 : s + 1;
        sp = (sp == NSTG - 1) ? 0 : sp + 1;
    }

    if (MODE == 2) {
        // -------- transposed epilogue: SMEM [n][m] staging (pad 132) --------
        __syncthreads();   // mainloop SMEM reads done in all warps
#pragma unroll
        for (int i = 0; i < 4; i++) {
            const int rr0 = wm + i * 16 + g;
            const int rr1 = rr0 + 8;
#pragma unroll
            for (int j = 0; j < 4; j++) {
                const int cc = wn + j * 8 + 2 * tig;
                const float b0 = bias[bn + cc];
                const float b1 = bias[bn + cc + 1];
                smf[(cc + 0) * 132 + rr0] = tf32r(acc[i][j][0] + b0);
                smf[(cc + 1) * 132 + rr0] = tf32r(acc[i][j][1] + b1);
                smf[(cc + 0) * 132 + rr1] = tf32r(acc[i][j][2] + b0);
                smf[(cc + 1) * 132 + rr1] = tf32r(acc[i][j][3] + b1);
            }
        }
        __syncthreads();
        // coalesced write: vT[(bn+nl)][bm + m], row = 128 floats
        const int nl = tid >> 1;
        const int m0 = (tid & 1) * 64;
        float* orow = Cb + (size_t)(bn + nl) * cM + bm + m0;
        const float* srow = smf + nl * 132 + m0;
#pragma unroll
        for (int u = 0; u < 16; u++) {
            float4 vv;
            vv.x = srow[u * 4 + 0];
            vv.y = srow[u * 4 + 1];
            vv.z = srow[u * 4 + 2];
            vv.w = srow[u * 4 + 3];
            *(float4*)(orow + u * 4) = vv;
        }
    } else {
#pragma unroll
        for (int i = 0; i < 4; i++) {
            const int rr0 = bm + wm + i * 16 + g;
            const int rr1 = rr0 + 8;
#pragma unroll
            for (int j = 0; j < 4; j++) {
                const int cc = bn + wn + j * 8 + 2 * tig;
                float b0 = 0.f, b1 = 0.f;
                if (bias) { b0 = bias[cc]; b1 = bias[cc + 1]; }
                float2 v0, v1;
                v0.x = acc[i][j][0] + b0; v0.y = acc[i][j][1] + b1;
                v1.x = acc[i][j][2] + b0; v1.y = acc[i][j][3] + b1;
                if (MODE == 1) {
                    v0.x = tf32r(v0.x); v0.y = tf32r(v0.y);
                    v1.x = tf32r(v1.x); v1.y = tf32r(v1.y);
                }
                *(float2*)(Cb + (size_t)rr0 * ldc + cc) = v0;
                *(float2*)(Cb + (size_t)rr1 * ldc + cc) = v1;
            }
        }
    }
}

// fused q/k/v projections: grid (16, 64, 3); z==2 writes vT directly
__global__ __launch_bounds__(256, 2)
void gemm3_proj(const float* __restrict__ bq, const float* __restrict__ bk,
                const float* __restrict__ bv) {
    const int z = blockIdx.z;
    const int bm = blockIdx.y * 128, bn = blockIdx.x * 128;
    if (z == 0)
        gemm_core<1>(g_qrot, g_wq, bq, g_q, cH, cH, cH, cH, bm, bn);
    else if (z == 1)
        gemm_core<1>(g_krot, g_wk, bk, g_k, cH, cH, cH, cH, bm, bn);
    else
        gemm_core<2>(g_vin, g_wv, bv, g_vT, cH, cH, cH, cM, bm, bn);
}

__global__ __launch_bounds__(256, 2)
void gemm_bat0(const float* __restrict__ A, const float* __restrict__ Bm,
               const float* __restrict__ bias, float* __restrict__ C,
               int Kd, int lda, int ldb, int ldc,
               size_t strA, size_t strB, size_t strC) {
    gemm_core<0>(A + blockIdx.z * strA, Bm + blockIdx.z * strB, bias,
                 C + blockIdx.z * strC, Kd, lda, ldb, ldc,
                 blockIdx.y * 128, blockIdx.x * 128);
}

__global__ __launch_bounds__(256, 2)
void gemm_bat1(const float* __restrict__ A, const float* __restrict__ Bm,
               const float* __restrict__ bias, float* __restrict__ C,
               int Kd, int lda, int ldb, int ldc,
               size_t strA, size_t strB, size_t strC) {
    gemm_core<1>(A + blockIdx.z * strA, Bm + blockIdx.z * strB, bias,
                 C + blockIdx.z * strC, Kd, lda, ldb, ldc,
                 blockIdx.y * 128, blockIdx.x * 128);
}

// ---------------- softmax ---------------------------------------------------
__global__ void softmax_kernel(float* __restrict__ Sc, float scale) {
    const size_t row = blockIdx.x;
    float* p = Sc + row * (size_t)cS;
    const int tid = threadIdx.x;
    __shared__ float smax[8];
    __shared__ float ssum[8];

    float v[8];
    float m = -CUDART_INF_F;
#pragma unroll
    for (int i = 0; i < 8; i++) {
        v[i] = p[tid + i * 256] * scale;
        m = fmaxf(m, v[i]);
    }
#pragma unroll
    for (int o = 16; o > 0; o >>= 1)
        m = fmaxf(m, __shfl_xor_sync(0xffffffffu, m, o));
    if ((tid & 31) == 0) smax[tid >> 5] = m;
    __syncthreads();
    m = smax[0];
#pragma unroll
    for (int w = 1; w < 8; w++) m = fmaxf(m, smax[w]);

    float s = 0.f;
#pragma unroll
    for (int i = 0; i < 8; i++) {
        v[i] = expf(v[i] - m);
        s += v[i];
    }
#pragma unroll
    for (int o = 16; o > 0; o >>= 1)
        s += __shfl_xor_sync(0xffffffffu, s, o);
    if ((tid & 31) == 0) ssum[tid >> 5] = s;
    __syncthreads();
    s = 0.f;
#pragma unroll
    for (int w = 0; w < 8; w++) s += ssum[w];
    const float inv = 1.0f / s;
#pragma unroll
    for (int i = 0; i < 8; i++) p[tid + i * 256] = tf32r(v[i] * inv);
}

// ---------------- launch ----------------------------------------------------
extern "C" void kernel_launch(void* const* d_in, const int* in_sizes, int n_in,
                              void* d_out, int out_size) {
    const float* query = (const float*)d_in[0];
    const float* key_  = (const float*)d_in[1];
    const float* value = (const float*)d_in[2];
    const float* Wq = (const float*)d_in[3];
    const float* bq = (const float*)d_in[4];
    const float* Wk = (const float*)d_in[5];
    const float* bk = (const float*)d_in[6];
    const float* Wv = (const float*)d_in[7];
    const float* bv = (const float*)d_in[8];
    const float* Wo = (const float*)d_in[9];
    const float* bo = (const float*)d_in[10];
    float* out = (float*)d_out;

    float *p_vT, *p_s, *p_ctx, *p_q, *p_k, *p_wo;
    cudaGetSymbolAddress((void**)&p_vT, g_vT);
    cudaGetSymbolAddress((void**)&p_s, g_s);
    cudaGetSymbolAddress((void**)&p_ctx, g_ctx);
    cudaGetSymbolAddress((void**)&p_q, g_q);
    cudaGetSymbolAddress((void**)&p_k, g_k);
    cudaGetSymbolAddress((void**)&p_wo, g_wo);

    cudaFuncSetAttribute(gemm3_proj,
                         cudaFuncAttributeMaxDynamicSharedMemorySize, GEMM_SMEM);
    cudaFuncSetAttribute(gemm_bat0,
                         cudaFuncAttributeMaxDynamicSharedMemorySize, GEMM_SMEM);
    cudaFuncSetAttribute(gemm_bat1,
                         cudaFuncAttributeMaxDynamicSharedMemorySize, GEMM_SMEM);

    // 1) RoPE tables; RoPE(q,k) + round(v) pair-processed
    rope_tables_kernel<<<(cS * cH2 + 255) / 256, 256>>>();
    rope_apply_v_kernel<<<(int)((size_t)cM * (cH2 / 4) / 256), 256>>>(query, key_, value);

    // 2) round all weights (one launch)
    round_weights_kernel<<<dim3((unsigned)(WN / 4 / 256), 4), 256>>>(Wq, Wk, Wv, Wo);

    // 3) fused q/k/v projections; v written directly transposed (g_vT)
    gemm3_proj<<<dim3(16, 64, 3), 256, GEMM_SMEM>>>(bq, bk, bv);

    // 4) scores = q @ k^T (batched over B)
    gemm_bat0<<<dim3(16, 16, cB), 256, GEMM_SMEM>>>(p_q, p_k, nullptr, p_s,
                                                    cH, cH, cH, cS, SH, SH, SSz);

    // 5) softmax
    const float scale = 1.0f / sqrtf((float)cH);
    softmax_kernel<<<cB * cS, 256>>>(p_s, scale);

    // 6) context = probs @ vT^T (batched)
    gemm_bat1<<<dim3(16, 16, cB), 256, GEMM_SMEM>>>(p_s, p_vT, nullptr, p_ctx,
                                                    cS, cS, cM, cH, SSz, (size_t)cS, SH);

    // 7) out = ctx @ Wo^T + bo
    gemm_bat0<<<dim3(16, 64, 1), 256, GEMM_SMEM>>>(p_ctx, p_wo, bo, out,
                                                   cH, cH, cH, cH, 0, 0, 0);
}